// round 11
// baseline (speedup 1.0000x reference)
#include <cuda_runtime.h>
#include <cuda_bf16.h>
#include <cstdint>

// ---------------- problem constants ----------------
#define MDIM 16384          // B*S
#define KD   1024           // d_model
#define NELEM ((size_t)MDIM * KD)
#define WELEM ((size_t)KD * KD)

// GEMM tiling: CTA 128x128, 8 warps (2x4), warp tile 64x32, BK=32 (4 k8-steps)
// 2 CTAs per SM for inter-CTA latency hiding.
#define TMC 128
#define TN  128
#define BK  32
#define NCH (KD / BK)                 // 32 chunks
#define PITCHB 144                    // smem row pitch bytes (128B data + 16B pad)
#define A_BYTES (128 * PITCHB)        // 18432
#define B_BYTES (128 * PITCHB)        // 18432
#define STAGE_BYTES (A_BYTES + B_BYTES)  // 36864
#define STAGES 3
#define SMEM_DYN (STAGES * STAGE_BYTES)  // 110592 (x2 CTAs = 221184 <= 227KB)
#define NTHR 256

// attn: 4 tokens per 256-thread block, 64 threads per token
#define ATOK 4
#define TOK_F 3344                     // floats per token: q1024 + k1024 + v1024 + at(16*17)
#define ATTN_SMEM (ATOK * TOK_F * 4)   // 53504 bytes

// ---------------- device scratch ----------------
__device__ float g_aq[NELEM], g_ak[NELEM], g_av[NELEM];   // tf32-rounded activations
__device__ float g_w[4][WELEM];                            // tf32-rounded weights
__device__ float g_q[NELEM], g_k[NELEM], g_v[NELEM];       // projections
__device__ float g_x[NELEM];                               // attn out (tf32-rounded)

// ---------------- PTX helpers ----------------
__device__ __forceinline__ uint32_t smem_u32(const void* p) {
    uint32_t a;
    asm("{ .reg .u64 t; cvta.to.shared.u64 t, %1; cvt.u32.u64 %0, t; }" : "=r"(a) : "l"(p));
    return a;
}
__device__ __forceinline__ void cp16(uint32_t dst, const void* src) {
    asm volatile("cp.async.cg.shared.global [%0], [%1], 16;" :: "r"(dst), "l"(src));
}
__device__ __forceinline__ void cp_commit() { asm volatile("cp.async.commit_group;"); }
__device__ __forceinline__ void ldm_x4(uint32_t r[4], uint32_t addr) {
    asm volatile("ldmatrix.sync.aligned.m8n8.x4.shared.b16 {%0,%1,%2,%3}, [%4];"
                 : "=r"(r[0]), "=r"(r[1]), "=r"(r[2]), "=r"(r[3]) : "r"(addr));
}
__device__ __forceinline__ void mma_tf32(float c[4], const uint32_t a[4],
                                         uint32_t b0, uint32_t b1) {
    asm volatile(
        "mma.sync.aligned.m16n8k8.row.col.f32.tf32.tf32.f32 "
        "{%0,%1,%2,%3}, {%4,%5,%6,%7}, {%8,%9}, {%0,%1,%2,%3};"
        : "+f"(c[0]), "+f"(c[1]), "+f"(c[2]), "+f"(c[3])
        : "r"(a[0]), "r"(a[1]), "r"(a[2]), "r"(a[3]), "r"(b0), "r"(b1));
}
__device__ __forceinline__ float tf32r(float x) {
    uint32_t u;
    asm("cvt.rna.tf32.f32 %0, %1;" : "=r"(u) : "f"(x));
    return __uint_as_float(u);
}

// ---------------- GEMM: C[16384,1024] = A*W^T + bias (tf32 single-pass) ----------------
__device__ __forceinline__ void tf32_gemm_body(
    const float* __restrict__ A, const float* __restrict__ W,
    const float* __restrict__ bias, float* __restrict__ C)
{
    extern __shared__ char dynsm[];
    const uint32_t sb = smem_u32(dynsm);

    const int t    = threadIdx.x;
    const int lane = t & 31;
    const int wid  = t >> 5;
    const int wm   = (wid >> 2) * 64;    // warp m offset (0/64)
    const int wn   = (wid & 3) * 32;     // warp n offset (0..96)
    const int m0   = blockIdx.y * TMC;
    const int n0   = blockIdx.x * TN;

    const char* pA = (const char*)A;
    const char* pW = (const char*)W;

    float acc[4][4][4];
#pragma unroll
    for (int i = 0; i < 4; i++)
#pragma unroll
        for (int j = 0; j < 4; j++)
#pragma unroll
            for (int r = 0; r < 4; r++) acc[i][j][r] = 0.f;

    const int sl[4] = {t, t + 256, t + 512, t + 768};

    auto load_chunk = [&](int c, int buf) {
        const uint32_t s  = sb + (uint32_t)buf * STAGE_BYTES;
        const uint32_t sB = s + A_BYTES;
        const size_t kb = (size_t)c * 128;
#pragma unroll
        for (int i = 0; i < 4; i++) {
            const int r = sl[i] >> 3, q = sl[i] & 7;
            const uint32_t off = (uint32_t)(r * PITCHB + q * 16);
            cp16(s  + off, pA + (size_t)(m0 + r) * 4096 + kb + q * 16);
            cp16(sB + off, pW + (size_t)(n0 + r) * 4096 + kb + q * 16);
        }
    };

    load_chunk(0, 0); cp_commit();
    load_chunk(1, 1); cp_commit();

    const int g  = lane >> 3;
    const int r8 = lane & 7;
    const uint32_t aBase = (uint32_t)((wm + (g & 1) * 8 + r8) * PITCHB + (g >> 1) * 16);
    const uint32_t bBase = (uint32_t)((wn + (g >> 1) * 8 + r8) * PITCHB + (g & 1) * 16);

#pragma unroll 1
    for (int c = 0; c < NCH; c++) {
        asm volatile("cp.async.wait_group 1;");
        __syncthreads();

        if (c + 2 < NCH) load_chunk(c + 2, (c + 2) % STAGES);
        cp_commit();

        const uint32_t s  = sb + (uint32_t)(c % STAGES) * STAGE_BYTES;
        const uint32_t sA = s;
        const uint32_t sB = s + A_BYTES;

#pragma unroll
        for (int ks = 0; ks < 4; ks++) {
            const uint32_t kb = (uint32_t)(ks * 32);
            uint32_t af[4][4], bf[2][4];
#pragma unroll
            for (int mt = 0; mt < 4; mt++)
                ldm_x4(af[mt], sA + aBase + (uint32_t)(mt * 16 * PITCHB) + kb);
#pragma unroll
            for (int nn = 0; nn < 2; nn++)
                ldm_x4(bf[nn], sB + bBase + (uint32_t)(nn * 16 * PITCHB) + kb);
#pragma unroll
            for (int mt = 0; mt < 4; mt++) {
#pragma unroll
                for (int j = 0; j < 4; j++) {
                    const int p = j >> 1, e = (j & 1) * 2;
                    mma_tf32(acc[mt][j], af[mt], bf[p][e], bf[p][e + 1]);
                }
            }
        }
    }

    const int tr = lane >> 2;
    const int tc = (lane & 3) * 2;
#pragma unroll
    for (int mt = 0; mt < 4; mt++) {
        const int gr = m0 + wm + mt * 16 + tr;
        float* row0 = C + (size_t)gr * KD + n0 + wn;
        float* row1 = row0 + 8 * KD;
#pragma unroll
        for (int j = 0; j < 4; j++) {
            const int gc = wn + j * 8 + tc;
            float2 bb = *(const float2*)(bias + n0 + gc);
            float2 o0, o1;
            o0.x = acc[mt][j][0] + bb.x;  o0.y = acc[mt][j][1] + bb.y;
            o1.x = acc[mt][j][2] + bb.x;  o1.y = acc[mt][j][3] + bb.y;
            *(float2*)(row0 + j * 8 + tc) = o0;
            *(float2*)(row1 + j * 8 + tc) = o1;
        }
    }
}

__global__ __launch_bounds__(NTHR, 2)
void qkv_mma_kernel(const float* __restrict__ bq, const float* __restrict__ bk,
                    const float* __restrict__ bv) {
    const int z = blockIdx.z;
    const float* A = (z == 0) ? g_aq : (z == 1) ? g_ak : g_av;
    const float* bias = (z == 0) ? bq : (z == 1) ? bk : bv;
    float* C = (z == 0) ? g_q : (z == 1) ? g_k : g_v;
    tf32_gemm_body(A, g_w[z], bias, C);
}

__global__ __launch_bounds__(NTHR, 2)
void out_mma_kernel(const float* __restrict__ bo, float* __restrict__ out) {
    tf32_gemm_body(g_x, g_w[3], bo, out);
}

// ---------------- tf32 rounding copy passes ----------------
__device__ __forceinline__ void round4(const float4 v, float* dst, size_t i4) {
    float4 o;
    o.x = tf32r(v.x); o.y = tf32r(v.y); o.z = tf32r(v.z); o.w = tf32r(v.w);
    ((float4*)dst)[i4] = o;
}

__global__ __launch_bounds__(256)
void round_act_kernel(const float* __restrict__ q, const float* __restrict__ k,
                      const float* __restrict__ v) {
    const int z = blockIdx.y;
    const float* src = (z == 0) ? q : (z == 1) ? k : v;
    float* dst = (z == 0) ? g_aq : (z == 1) ? g_ak : g_av;
    const size_t n4 = NELEM / 4;
    const size_t stride = (size_t)gridDim.x * blockDim.x;
    for (size_t i = (size_t)blockIdx.x * blockDim.x + threadIdx.x; i < n4; i += stride)
        round4(((const float4*)src)[i], dst, i);
}

__global__ __launch_bounds__(256)
void round_w_kernel(const float* __restrict__ wq, const float* __restrict__ wk,
                    const float* __restrict__ wv, const float* __restrict__ wo) {
    const int z = blockIdx.y;
    const float* src = (z == 0) ? wq : (z == 1) ? wk : (z == 2) ? wv : wo;
    float* dst = g_w[z];
    const size_t n4 = WELEM / 4;
    const size_t stride = (size_t)gridDim.x * blockDim.x;
    for (size_t i = (size_t)blockIdx.x * blockDim.x + threadIdx.x; i < n4; i += stride)
        round4(((const float4*)src)[i], dst, i);
}

// ---------------- per-token head attention, 2x2 register tiling ----------------
// 4 tokens per 256-thread block; 64 threads per token.
// Score: thread (hp,gp) computes 2x2 of the 16x16 score tile.
// AV:    thread (hp,cp) computes rows {2hp,2hp+1} x float4-cols {2cp,2cp+1}.
__global__ __launch_bounds__(256)
void attn_kernel() {
    extern __shared__ float asmem[];
    const int t    = threadIdx.x;
    const int grp  = t >> 6;       // token slot in block
    const int s64  = t & 63;
    const int token = blockIdx.x * ATOK + grp;
    const int b = token >> 12;
    const int s = token & 4095;

    float* qs = asmem + grp * TOK_F;
    float* ks = qs + 1024;
    float* vs = ks + 1024;
    float* at = vs + 1024;         // [16][17]

    const size_t base = (size_t)token * 1024;
    {
        const float4* gq = (const float4*)(g_q + base);
        const float4* gk = (const float4*)(g_k + base);
        const float4* gv = (const float4*)(g_v + base);
#pragma unroll
        for (int i = 0; i < 4; i++) {
            const int slot = s64 + i * 64;           // 0..255
            ((float4*)qs)[slot] = gq[slot];
            ((float4*)ks)[slot] = gk[slot];
            ((float4*)vs)[slot] = gv[slot];
        }
    }
    __syncthreads();

    const int hp = s64 >> 3;       // 0..7
    const int gp = s64 & 7;        // 0..7

    // ---- score phase: 2x2 tile, d ascending ----
    {
        float a00 = 0.f, a01 = 0.f, a10 = 0.f, a11 = 0.f;
        const float4* q4 = (const float4*)qs;
        const float4* k4 = (const float4*)ks;
#pragma unroll
        for (int j = 0; j < 16; j++) {
            float4 q0 = q4[(2 * hp) * 16 + j];
            float4 q1 = q4[(2 * hp + 1) * 16 + j];
            float4 k0 = k4[(2 * gp) * 16 + j];
            float4 k1 = k4[(2 * gp + 1) * 16 + j];
            a00 += q0.x * k0.x + q0.y * k0.y + q0.z * k0.z + q0.w * k0.w;
            a01 += q0.x * k1.x + q0.y * k1.y + q0.z * k1.z + q0.w * k1.w;
            a10 += q1.x * k0.x + q1.y * k0.y + q1.z * k0.z + q1.w * k0.w;
            a11 += q1.x * k1.x + q1.y * k1.y + q1.z * k1.z + q1.w * k1.w;
        }
        at[(2 * hp) * 17 + 2 * gp]         = a00 * 0.125f;
        at[(2 * hp) * 17 + 2 * gp + 1]     = a01 * 0.125f;
        at[(2 * hp + 1) * 17 + 2 * gp]     = a10 * 0.125f;
        at[(2 * hp + 1) * 17 + 2 * gp + 1] = a11 * 0.125f;
    }
    __syncthreads();

    // ---- softmax: 16 threads per token, one row each ----
    if (s64 < 16) {
        float* row = at + s64 * 17;
        float mx = row[0];
#pragma unroll
        for (int j = 1; j < 16; j++) mx = fmaxf(mx, row[j]);
        float p[16];
        float sum = 0.f;
#pragma unroll
        for (int j = 0; j < 16; j++) { p[j] = __expf(row[j] - mx); sum += p[j]; }
        const float inv = 1.f / sum;
#pragma unroll
        for (int j = 0; j < 16; j++) row[j] = p[j] * inv;
    }
    __syncthreads();

    // ---- AV phase: rows {2hp,2hp+1}, float4 cols {2cp,2cp+1}, gg ascending ----
    const int cp = gp;
    float4 o00 = make_float4(0.f, 0.f, 0.f, 0.f), o01 = o00, o10 = o00, o11 = o00;
    const float4* v4 = (const float4*)vs;
#pragma unroll
    for (int gg = 0; gg < 16; gg++) {
        const float w0 = at[(2 * hp) * 17 + gg];
        const float w1 = at[(2 * hp + 1) * 17 + gg];
        const float4 va = v4[gg * 16 + 2 * cp];
        const float4 vb = v4[gg * 16 + 2 * cp + 1];
        o00.x += w0 * va.x; o00.y += w0 * va.y; o00.z += w0 * va.z; o00.w += w0 * va.w;
        o01.x += w0 * vb.x; o01.y += w0 * vb.y; o01.z += w0 * vb.z; o01.w += w0 * vb.w;
        o10.x += w1 * va.x; o10.y += w1 * va.y; o10.z += w1 * va.z; o10.w += w1 * va.w;
        o11.x += w1 * vb.x; o11.y += w1 * vb.y; o11.z += w1 * vb.z; o11.w += w1 * vb.w;
    }

    // scrambled layout + tf32 rounding (feeds the tf32 out-GEMM)
    const int scol = (s & 15) * 64;
    const int srow = s >> 4;
#pragma unroll
    for (int e = 0; e < 2; e++) {
        const int h2 = 2 * hp + e;
        const size_t row = (size_t)b * 4096 + (size_t)h2 * 256 + srow;
        float4 oa = e ? o10 : o00;
        float4 ob = e ? o11 : o01;
        float4 ra, rb;
        ra.x = tf32r(oa.x); ra.y = tf32r(oa.y); ra.z = tf32r(oa.z); ra.w = tf32r(oa.w);
        rb.x = tf32r(ob.x); rb.y = tf32r(ob.y); rb.z = tf32r(ob.z); rb.w = tf32r(ob.w);
        *(float4*)(g_x + row * 1024 + scol + (2 * cp) * 4)     = ra;
        *(float4*)(g_x + row * 1024 + scol + (2 * cp + 1) * 4) = rb;
    }
}

// ---------------- launch ----------------
extern "C" void kernel_launch(void* const* d_in, const int* in_sizes, int n_in,
                              void* d_out, int out_size) {
    (void)in_sizes; (void)n_in; (void)out_size;
    const float* query = (const float*)d_in[0];
    const float* key   = (const float*)d_in[1];
    const float* value = (const float*)d_in[2];
    const float* Wq = (const float*)d_in[3];
    const float* bq = (const float*)d_in[4];
    const float* Wk = (const float*)d_in[5];
    const float* bk = (const float*)d_in[6];
    const float* Wv = (const float*)d_in[7];
    const float* bv = (const float*)d_in[8];
    const float* Wo = (const float*)d_in[9];
    const float* bo = (const float*)d_in[10];
    float* out = (float*)d_out;

    cudaFuncSetAttribute(qkv_mma_kernel, cudaFuncAttributeMaxDynamicSharedMemorySize, SMEM_DYN);
    cudaFuncSetAttribute(out_mma_kernel, cudaFuncAttributeMaxDynamicSharedMemorySize, SMEM_DYN);
    cudaFuncSetAttribute(attn_kernel, cudaFuncAttributeMaxDynamicSharedMemorySize, ATTN_SMEM);

    round_act_kernel<<<dim3(4096, 3), 256>>>(query, key, value);
    round_w_kernel<<<dim3(1024, 4), 256>>>(Wq, Wk, Wv, Wo);
    qkv_mma_kernel<<<dim3(KD / TN, MDIM / TMC, 3), NTHR, SMEM_DYN>>>(bq, bk, bv);
    attn_kernel<<<MDIM / ATOK, 256, ATTN_SMEM>>>();
    out_mma_kernel<<<dim3(KD / TN, MDIM / TMC, 1), NTHR, SMEM_DYN>>>(bo, out);
}

// round 12
// speedup vs baseline: 1.1270x; 1.1270x over previous
#include <cuda_runtime.h>
#include <cuda_bf16.h>
#include <cstdint>

// ---------------- problem constants ----------------
#define MDIM 16384          // B*S
#define KD   1024           // d_model
#define NELEM ((size_t)MDIM * KD)
#define WELEM ((size_t)KD * KD)

// GEMM tiling: CTA 128x128, 8 warps (2x4), warp tile 64x32, BK=32 (4 k8-steps)
// 2 CTAs per SM for inter-CTA latency hiding.
#define TMC 128
#define TN  128
#define BK  32
#define NCH (KD / BK)                 // 32 chunks
#define PITCHB 144                    // smem row pitch bytes (128B data + 16B pad)
#define A_BYTES (128 * PITCHB)        // 18432
#define B_BYTES (128 * PITCHB)        // 18432
#define STAGE_BYTES (A_BYTES + B_BYTES)  // 36864
#define STAGES 3
#define SMEM_DYN (STAGES * STAGE_BYTES)  // 110592 (x2 CTAs = 221184 <= 227KB)
#define NTHR 256

// attn: 4 tokens per 256-thread block, 64 threads per token
#define ATOK 4
#define TOK_F 3344                     // floats per token: q1024 + k1024 + v1024 + at(16*17)
#define ATTN_SMEM (ATOK * TOK_F * 4)   // 53504 bytes

// ---------------- device scratch ----------------
__device__ float g_aq[NELEM], g_ak[NELEM], g_av[NELEM];   // tf32-rounded activations
__device__ float g_w[4][WELEM];                            // tf32-rounded weights
__device__ float g_q[NELEM], g_k[NELEM], g_v[NELEM];       // projections
__device__ float g_x[NELEM];                               // attn out (tf32-rounded)

// ---------------- PTX helpers ----------------
__device__ __forceinline__ uint32_t smem_u32(const void* p) {
    uint32_t a;
    asm("{ .reg .u64 t; cvta.to.shared.u64 t, %1; cvt.u32.u64 %0, t; }" : "=r"(a) : "l"(p));
    return a;
}
__device__ __forceinline__ void cp16(uint32_t dst, const void* src) {
    asm volatile("cp.async.cg.shared.global [%0], [%1], 16;" :: "r"(dst), "l"(src));
}
__device__ __forceinline__ void cp_commit() { asm volatile("cp.async.commit_group;"); }
__device__ __forceinline__ void ldm_x4(uint32_t r[4], uint32_t addr) {
    asm volatile("ldmatrix.sync.aligned.m8n8.x4.shared.b16 {%0,%1,%2,%3}, [%4];"
                 : "=r"(r[0]), "=r"(r[1]), "=r"(r[2]), "=r"(r[3]) : "r"(addr));
}
__device__ __forceinline__ void mma_tf32(float c[4], const uint32_t a[4],
                                         uint32_t b0, uint32_t b1) {
    asm volatile(
        "mma.sync.aligned.m16n8k8.row.col.f32.tf32.tf32.f32 "
        "{%0,%1,%2,%3}, {%4,%5,%6,%7}, {%8,%9}, {%0,%1,%2,%3};"
        : "+f"(c[0]), "+f"(c[1]), "+f"(c[2]), "+f"(c[3])
        : "r"(a[0]), "r"(a[1]), "r"(a[2]), "r"(a[3]), "r"(b0), "r"(b1));
}
__device__ __forceinline__ float tf32r(float x) {
    uint32_t u;
    asm("cvt.rna.tf32.f32 %0, %1;" : "=r"(u) : "f"(x));
    return __uint_as_float(u);
}

// ---------------- GEMM: C[16384,1024] = A*W^T + bias (tf32 single-pass) ----------------
__device__ __forceinline__ void tf32_gemm_body(
    const float* __restrict__ A, const float* __restrict__ W,
    const float* __restrict__ bias, float* __restrict__ C)
{
    extern __shared__ char dynsm[];
    const uint32_t sb = smem_u32(dynsm);

    const int t    = threadIdx.x;
    const int lane = t & 31;
    const int wid  = t >> 5;
    const int wm   = (wid >> 2) * 64;    // warp m offset (0/64)
    const int wn   = (wid & 3) * 32;     // warp n offset (0..96)
    const int m0   = blockIdx.y * TMC;
    const int n0   = blockIdx.x * TN;

    const char* pA = (const char*)A;
    const char* pW = (const char*)W;

    float acc[4][4][4];
#pragma unroll
    for (int i = 0; i < 4; i++)
#pragma unroll
        for (int j = 0; j < 4; j++)
#pragma unroll
            for (int r = 0; r < 4; r++) acc[i][j][r] = 0.f;

    const int sl[4] = {t, t + 256, t + 512, t + 768};

    auto load_chunk = [&](int c, int buf) {
        const uint32_t s  = sb + (uint32_t)buf * STAGE_BYTES;
        const uint32_t sB = s + A_BYTES;
        const size_t kb = (size_t)c * 128;
#pragma unroll
        for (int i = 0; i < 4; i++) {
            const int r = sl[i] >> 3, q = sl[i] & 7;
            const uint32_t off = (uint32_t)(r * PITCHB + q * 16);
            cp16(s  + off, pA + (size_t)(m0 + r) * 4096 + kb + q * 16);
            cp16(sB + off, pW + (size_t)(n0 + r) * 4096 + kb + q * 16);
        }
    };

    load_chunk(0, 0); cp_commit();
    load_chunk(1, 1); cp_commit();

    const int g  = lane >> 3;
    const int r8 = lane & 7;
    const uint32_t aBase = (uint32_t)((wm + (g & 1) * 8 + r8) * PITCHB + (g >> 1) * 16);
    const uint32_t bBase = (uint32_t)((wn + (g >> 1) * 8 + r8) * PITCHB + (g & 1) * 16);

#pragma unroll 1
    for (int c = 0; c < NCH; c++) {
        asm volatile("cp.async.wait_group 1;");
        __syncthreads();

        if (c + 2 < NCH) load_chunk(c + 2, (c + 2) % STAGES);
        cp_commit();

        const uint32_t s  = sb + (uint32_t)(c % STAGES) * STAGE_BYTES;
        const uint32_t sA = s;
        const uint32_t sB = s + A_BYTES;

#pragma unroll
        for (int ks = 0; ks < 4; ks++) {
            const uint32_t kb = (uint32_t)(ks * 32);
            uint32_t af[4][4], bf[2][4];
#pragma unroll
            for (int mt = 0; mt < 4; mt++)
                ldm_x4(af[mt], sA + aBase + (uint32_t)(mt * 16 * PITCHB) + kb);
#pragma unroll
            for (int nn = 0; nn < 2; nn++)
                ldm_x4(bf[nn], sB + bBase + (uint32_t)(nn * 16 * PITCHB) + kb);
#pragma unroll
            for (int mt = 0; mt < 4; mt++) {
#pragma unroll
                for (int j = 0; j < 4; j++) {
                    const int p = j >> 1, e = (j & 1) * 2;
                    mma_tf32(acc[mt][j], af[mt], bf[p][e], bf[p][e + 1]);
                }
            }
        }
    }

    const int tr = lane >> 2;
    const int tc = (lane & 3) * 2;
#pragma unroll
    for (int mt = 0; mt < 4; mt++) {
        const int gr = m0 + wm + mt * 16 + tr;
        float* row0 = C + (size_t)gr * KD + n0 + wn;
        float* row1 = row0 + 8 * KD;
#pragma unroll
        for (int j = 0; j < 4; j++) {
            const int gc = wn + j * 8 + tc;
            float2 bb = *(const float2*)(bias + n0 + gc);
            float2 o0, o1;
            o0.x = acc[mt][j][0] + bb.x;  o0.y = acc[mt][j][1] + bb.y;
            o1.x = acc[mt][j][2] + bb.x;  o1.y = acc[mt][j][3] + bb.y;
            *(float2*)(row0 + j * 8 + tc) = o0;
            *(float2*)(row1 + j * 8 + tc) = o1;
        }
    }
}

__global__ __launch_bounds__(NTHR, 2)
void qkv_mma_kernel(const float* __restrict__ bq, const float* __restrict__ bk,
                    const float* __restrict__ bv) {
    const int z = blockIdx.z;
    const float* A = (z == 0) ? g_aq : (z == 1) ? g_ak : g_av;
    const float* bias = (z == 0) ? bq : (z == 1) ? bk : bv;
    float* C = (z == 0) ? g_q : (z == 1) ? g_k : g_v;
    tf32_gemm_body(A, g_w[z], bias, C);
}

__global__ __launch_bounds__(NTHR, 2)
void out_mma_kernel(const float* __restrict__ bo, float* __restrict__ out) {
    tf32_gemm_body(g_x, g_w[3], bo, out);
}

// ---------------- tf32 rounding copy passes ----------------
__device__ __forceinline__ void round4(const float4 v, float* dst, size_t i4) {
    float4 o;
    o.x = tf32r(v.x); o.y = tf32r(v.y); o.z = tf32r(v.z); o.w = tf32r(v.w);
    ((float4*)dst)[i4] = o;
}

__global__ __launch_bounds__(256)
void round_act_kernel(const float* __restrict__ q, const float* __restrict__ k,
                      const float* __restrict__ v) {
    const int z = blockIdx.y;
    const float* src = (z == 0) ? q : (z == 1) ? k : v;
    float* dst = (z == 0) ? g_aq : (z == 1) ? g_ak : g_av;
    const size_t n4 = NELEM / 4;
    const size_t stride = (size_t)gridDim.x * blockDim.x;
    for (size_t i = (size_t)blockIdx.x * blockDim.x + threadIdx.x; i < n4; i += stride)
        round4(((const float4*)src)[i], dst, i);
}

__global__ __launch_bounds__(256)
void round_w_kernel(const float* __restrict__ wq, const float* __restrict__ wk,
                    const float* __restrict__ wv, const float* __restrict__ wo) {
    const int z = blockIdx.y;
    const float* src = (z == 0) ? wq : (z == 1) ? wk : (z == 2) ? wv : wo;
    float* dst = g_w[z];
    const size_t n4 = WELEM / 4;
    const size_t stride = (size_t)gridDim.x * blockDim.x;
    for (size_t i = (size_t)blockIdx.x * blockDim.x + threadIdx.x; i < n4; i += stride)
        round4(((const float4*)src)[i], dst, i);
}

// ---------------- per-token head attention, 2x2 tiling, conflict-free smem ----------------
// 4 tokens per 256-thread block; 64 threads per token (hp = s64>>3, gp/cp = s64&7).
// k tile is XOR-swizzled: float4-col c of row r stored at slot (c ^ (r>>1)).
// AV phase splits columns as {cp, cp+8} (natural v layout -> distinct bank groups).
__global__ __launch_bounds__(256)
void attn_kernel() {
    extern __shared__ float asmem[];
    const int t    = threadIdx.x;
    const int grp  = t >> 6;       // token slot in block
    const int s64  = t & 63;
    const int token = blockIdx.x * ATOK + grp;
    const int b = token >> 12;
    const int s = token & 4095;

    float* qs = asmem + grp * TOK_F;
    float* ks = qs + 1024;
    float* vs = ks + 1024;
    float* at = vs + 1024;         // [16][17]

    const size_t base = (size_t)token * 1024;
    {
        const float4* gq = (const float4*)(g_q + base);
        const float4* gk = (const float4*)(g_k + base);
        const float4* gv = (const float4*)(g_v + base);
#pragma unroll
        for (int i = 0; i < 4; i++) {
            const int slot = s64 + i * 64;           // 0..255
            const int r = slot >> 4, c = slot & 15;
            ((float4*)qs)[slot] = gq[slot];
            ((float4*)vs)[slot] = gv[slot];
            ((float4*)ks)[r * 16 + (c ^ ((r >> 1) & 7))] = gk[slot];
        }
    }
    __syncthreads();

    const int hp = s64 >> 3;       // 0..7
    const int gp = s64 & 7;        // 0..7

    // ---- score phase: 2x2 tile, d ascending; k via XOR-swizzled slots ----
    {
        float a00 = 0.f, a01 = 0.f, a10 = 0.f, a11 = 0.f;
        const float4* q4 = (const float4*)qs;
        const float4* k4 = (const float4*)ks;
#pragma unroll
        for (int j = 0; j < 16; j++) {
            const int js = j ^ gp;                 // swizzled col slot (r>>1 == gp)
            float4 q0 = q4[(2 * hp) * 16 + j];
            float4 q1 = q4[(2 * hp + 1) * 16 + j];
            float4 k0 = k4[(2 * gp) * 16 + js];
            float4 k1 = k4[(2 * gp + 1) * 16 + js];
            a00 += q0.x * k0.x + q0.y * k0.y + q0.z * k0.z + q0.w * k0.w;
            a01 += q0.x * k1.x + q0.y * k1.y + q0.z * k1.z + q0.w * k1.w;
            a10 += q1.x * k0.x + q1.y * k0.y + q1.z * k0.z + q1.w * k0.w;
            a11 += q1.x * k1.x + q1.y * k1.y + q1.z * k1.z + q1.w * k1.w;
        }
        at[(2 * hp) * 17 + 2 * gp]         = a00 * 0.125f;
        at[(2 * hp) * 17 + 2 * gp + 1]     = a01 * 0.125f;
        at[(2 * hp + 1) * 17 + 2 * gp]     = a10 * 0.125f;
        at[(2 * hp + 1) * 17 + 2 * gp + 1] = a11 * 0.125f;
    }
    __syncthreads();

    // ---- softmax: 16 threads per token, one row each ----
    if (s64 < 16) {
        float* row = at + s64 * 17;
        float mx = row[0];
#pragma unroll
        for (int j = 1; j < 16; j++) mx = fmaxf(mx, row[j]);
        float p[16];
        float sum = 0.f;
#pragma unroll
        for (int j = 0; j < 16; j++) { p[j] = __expf(row[j] - mx); sum += p[j]; }
        const float inv = 1.f / sum;
#pragma unroll
        for (int j = 0; j < 16; j++) row[j] = p[j] * inv;
    }
    __syncthreads();

    // ---- AV phase: rows {2hp,2hp+1}, float4-cols {cp, cp+8}, gg ascending ----
    const int cp = gp;
    float4 o00 = make_float4(0.f, 0.f, 0.f, 0.f), o01 = o00, o10 = o00, o11 = o00;
    const float4* v4 = (const float4*)vs;
#pragma unroll
    for (int gg = 0; gg < 16; gg++) {
        const float w0 = at[(2 * hp) * 17 + gg];
        const float w1 = at[(2 * hp + 1) * 17 + gg];
        const float4 va = v4[gg * 16 + cp];
        const float4 vb = v4[gg * 16 + cp + 8];
        o00.x += w0 * va.x; o00.y += w0 * va.y; o00.z += w0 * va.z; o00.w += w0 * va.w;
        o01.x += w0 * vb.x; o01.y += w0 * vb.y; o01.z += w0 * vb.z; o01.w += w0 * vb.w;
        o10.x += w1 * va.x; o10.y += w1 * va.y; o10.z += w1 * va.z; o10.w += w1 * va.w;
        o11.x += w1 * vb.x; o11.y += w1 * vb.y; o11.z += w1 * vb.z; o11.w += w1 * vb.w;
    }

    // scrambled layout + tf32 rounding (feeds the tf32 out-GEMM)
    const int scol = (s & 15) * 64;
    const int srow = s >> 4;
#pragma unroll
    for (int e = 0; e < 2; e++) {
        const int h2 = 2 * hp + e;
        const size_t row = (size_t)b * 4096 + (size_t)h2 * 256 + srow;
        float4 oa = e ? o10 : o00;
        float4 ob = e ? o11 : o01;
        float4 ra, rb;
        ra.x = tf32r(oa.x); ra.y = tf32r(oa.y); ra.z = tf32r(oa.z); ra.w = tf32r(oa.w);
        rb.x = tf32r(ob.x); rb.y = tf32r(ob.y); rb.z = tf32r(ob.z); rb.w = tf32r(ob.w);
        *(float4*)(g_x + row * 1024 + scol + cp * 4)       = ra;
        *(float4*)(g_x + row * 1024 + scol + (cp + 8) * 4) = rb;
    }
}

// ---------------- launch ----------------
extern "C" void kernel_launch(void* const* d_in, const int* in_sizes, int n_in,
                              void* d_out, int out_size) {
    (void)in_sizes; (void)n_in; (void)out_size;
    const float* query = (const float*)d_in[0];
    const float* key   = (const float*)d_in[1];
    const float* value = (const float*)d_in[2];
    const float* Wq = (const float*)d_in[3];
    const float* bq = (const float*)d_in[4];
    const float* Wk = (const float*)d_in[5];
    const float* bk = (const float*)d_in[6];
    const float* Wv = (const float*)d_in[7];
    const float* bv = (const float*)d_in[8];
    const float* Wo = (const float*)d_in[9];
    const float* bo = (const float*)d_in[10];
    float* out = (float*)d_out;

    cudaFuncSetAttribute(qkv_mma_kernel, cudaFuncAttributeMaxDynamicSharedMemorySize, SMEM_DYN);
    cudaFuncSetAttribute(out_mma_kernel, cudaFuncAttributeMaxDynamicSharedMemorySize, SMEM_DYN);
    cudaFuncSetAttribute(attn_kernel, cudaFuncAttributeMaxDynamicSharedMemorySize, ATTN_SMEM);

    round_act_kernel<<<dim3(4096, 3), 256>>>(query, key, value);
    round_w_kernel<<<dim3(1024, 4), 256>>>(Wq, Wk, Wv, Wo);
    qkv_mma_kernel<<<dim3(KD / TN, MDIM / TMC, 3), NTHR, SMEM_DYN>>>(bq, bk, bv);
    attn_kernel<<<MDIM / ATOK, 256, ATTN_SMEM>>>();
    out_mma_kernel<<<dim3(KD / TN, MDIM / TMC, 1), NTHR, SMEM_DYN>>>(bo, out);
}

// round 13
// speedup vs baseline: 1.1351x; 1.0072x over previous
#include <cuda_runtime.h>
#include <cuda_bf16.h>
#include <cstdint>

// ---------------- problem constants ----------------
#define MDIM 16384          // B*S
#define KD   1024           // d_model
#define NELEM ((size_t)MDIM * KD)
#define WELEM ((size_t)KD * KD)

// GEMM tiling: CTA 128x128, 8 warps (2x4), warp tile 64x32, BK=32 (4 k8-steps)
// 2 CTAs per SM for inter-CTA latency hiding.
#define TMC 128
#define TN  128
#define BK  32
#define NCH (KD / BK)                 // 32 chunks
#define PITCHB 144                    // smem row pitch bytes (128B data + 16B pad)
#define A_BYTES (128 * PITCHB)        // 18432
#define B_BYTES (128 * PITCHB)        // 18432
#define STAGE_BYTES (A_BYTES + B_BYTES)  // 36864
#define STAGES 3
#define SMEM_DYN (STAGES * STAGE_BYTES)  // 110592 (x2 CTAs = 221184 <= 227KB)
#define NTHR 256

// attn: 4 tokens per 256-thread block, 64 threads per token; q read direct from L1
#define ATOK 4
#define TOK_F 2320                     // floats per token: k1024 + v1024 + at(16*17)
#define ATTN_SMEM (ATOK * TOK_F * 4)   // 37120 bytes -> 6 CTAs/SM

// ---------------- device scratch ----------------
__device__ float g_aq[NELEM], g_ak[NELEM], g_av[NELEM];   // tf32-rounded activations
__device__ float g_w[4][WELEM];                            // tf32-rounded weights
__device__ float g_q[NELEM], g_k[NELEM], g_v[NELEM];       // projections
__device__ float g_x[NELEM];                               // attn out (tf32-rounded)

// ---------------- PTX helpers ----------------
__device__ __forceinline__ uint32_t smem_u32(const void* p) {
    uint32_t a;
    asm("{ .reg .u64 t; cvta.to.shared.u64 t, %1; cvt.u32.u64 %0, t; }" : "=r"(a) : "l"(p));
    return a;
}
__device__ __forceinline__ void cp16(uint32_t dst, const void* src) {
    asm volatile("cp.async.cg.shared.global [%0], [%1], 16;" :: "r"(dst), "l"(src));
}
__device__ __forceinline__ void cp_commit() { asm volatile("cp.async.commit_group;"); }
__device__ __forceinline__ void ldm_x4(uint32_t r[4], uint32_t addr) {
    asm volatile("ldmatrix.sync.aligned.m8n8.x4.shared.b16 {%0,%1,%2,%3}, [%4];"
                 : "=r"(r[0]), "=r"(r[1]), "=r"(r[2]), "=r"(r[3]) : "r"(addr));
}
__device__ __forceinline__ void mma_tf32(float c[4], const uint32_t a[4],
                                         uint32_t b0, uint32_t b1) {
    asm volatile(
        "mma.sync.aligned.m16n8k8.row.col.f32.tf32.tf32.f32 "
        "{%0,%1,%2,%3}, {%4,%5,%6,%7}, {%8,%9}, {%0,%1,%2,%3};"
        : "+f"(c[0]), "+f"(c[1]), "+f"(c[2]), "+f"(c[3])
        : "r"(a[0]), "r"(a[1]), "r"(a[2]), "r"(a[3]), "r"(b0), "r"(b1));
}
__device__ __forceinline__ float tf32r(float x) {
    uint32_t u;
    asm("cvt.rna.tf32.f32 %0, %1;" : "=r"(u) : "f"(x));
    return __uint_as_float(u);
}

// ---------------- GEMM: C[16384,1024] = A*W^T + bias (tf32 single-pass) ----------------
__device__ __forceinline__ void tf32_gemm_body(
    const float* __restrict__ A, const float* __restrict__ W,
    const float* __restrict__ bias, float* __restrict__ C)
{
    extern __shared__ char dynsm[];
    const uint32_t sb = smem_u32(dynsm);

    const int t    = threadIdx.x;
    const int lane = t & 31;
    const int wid  = t >> 5;
    const int wm   = (wid >> 2) * 64;    // warp m offset (0/64)
    const int wn   = (wid & 3) * 32;     // warp n offset (0..96)
    const int m0   = blockIdx.y * TMC;
    const int n0   = blockIdx.x * TN;

    const char* pA = (const char*)A;
    const char* pW = (const char*)W;

    float acc[4][4][4];
#pragma unroll
    for (int i = 0; i < 4; i++)
#pragma unroll
        for (int j = 0; j < 4; j++)
#pragma unroll
            for (int r = 0; r < 4; r++) acc[i][j][r] = 0.f;

    const int sl[4] = {t, t + 256, t + 512, t + 768};

    auto load_chunk = [&](int c, int buf) {
        const uint32_t s  = sb + (uint32_t)buf * STAGE_BYTES;
        const uint32_t sB = s + A_BYTES;
        const size_t kb = (size_t)c * 128;
#pragma unroll
        for (int i = 0; i < 4; i++) {
            const int r = sl[i] >> 3, q = sl[i] & 7;
            const uint32_t off = (uint32_t)(r * PITCHB + q * 16);
            cp16(s  + off, pA + (size_t)(m0 + r) * 4096 + kb + q * 16);
            cp16(sB + off, pW + (size_t)(n0 + r) * 4096 + kb + q * 16);
        }
    };

    load_chunk(0, 0); cp_commit();
    load_chunk(1, 1); cp_commit();

    const int g  = lane >> 3;
    const int r8 = lane & 7;
    const uint32_t aBase = (uint32_t)((wm + (g & 1) * 8 + r8) * PITCHB + (g >> 1) * 16);
    const uint32_t bBase = (uint32_t)((wn + (g >> 1) * 8 + r8) * PITCHB + (g & 1) * 16);

#pragma unroll 1
    for (int c = 0; c < NCH; c++) {
        asm volatile("cp.async.wait_group 1;");
        __syncthreads();

        if (c + 2 < NCH) load_chunk(c + 2, (c + 2) % STAGES);
        cp_commit();

        const uint32_t s  = sb + (uint32_t)(c % STAGES) * STAGE_BYTES;
        const uint32_t sA = s;
        const uint32_t sB = s + A_BYTES;

#pragma unroll
        for (int ks = 0; ks < 4; ks++) {
            const uint32_t kb = (uint32_t)(ks * 32);
            uint32_t af[4][4], bf[2][4];
#pragma unroll
            for (int mt = 0; mt < 4; mt++)
                ldm_x4(af[mt], sA + aBase + (uint32_t)(mt * 16 * PITCHB) + kb);
#pragma unroll
            for (int nn = 0; nn < 2; nn++)
                ldm_x4(bf[nn], sB + bBase + (uint32_t)(nn * 16 * PITCHB) + kb);
#pragma unroll
            for (int mt = 0; mt < 4; mt++) {
#pragma unroll
                for (int j = 0; j < 4; j++) {
                    const int p = j >> 1, e = (j & 1) * 2;
                    mma_tf32(acc[mt][j], af[mt], bf[p][e], bf[p][e + 1]);
                }
            }
        }
    }

    const int tr = lane >> 2;
    const int tc = (lane & 3) * 2;
#pragma unroll
    for (int mt = 0; mt < 4; mt++) {
        const int gr = m0 + wm + mt * 16 + tr;
        float* row0 = C + (size_t)gr * KD + n0 + wn;
        float* row1 = row0 + 8 * KD;
#pragma unroll
        for (int j = 0; j < 4; j++) {
            const int gc = wn + j * 8 + tc;
            float2 bb = *(const float2*)(bias + n0 + gc);
            float2 o0, o1;
            o0.x = acc[mt][j][0] + bb.x;  o0.y = acc[mt][j][1] + bb.y;
            o1.x = acc[mt][j][2] + bb.x;  o1.y = acc[mt][j][3] + bb.y;
            *(float2*)(row0 + j * 8 + tc) = o0;
            *(float2*)(row1 + j * 8 + tc) = o1;
        }
    }
}

__global__ __launch_bounds__(NTHR, 2)
void qkv_mma_kernel(const float* __restrict__ bq, const float* __restrict__ bk,
                    const float* __restrict__ bv) {
    const int z = blockIdx.z;
    const float* A = (z == 0) ? g_aq : (z == 1) ? g_ak : g_av;
    const float* bias = (z == 0) ? bq : (z == 1) ? bk : bv;
    float* C = (z == 0) ? g_q : (z == 1) ? g_k : g_v;
    tf32_gemm_body(A, g_w[z], bias, C);
}

__global__ __launch_bounds__(NTHR, 2)
void out_mma_kernel(const float* __restrict__ bo, float* __restrict__ out) {
    tf32_gemm_body(g_x, g_w[3], bo, out);
}

// ---------------- tf32 rounding: single fused pass (acts + weights) ----------------
__device__ __forceinline__ void round4(const float4 v, float* dst, size_t i4) {
    float4 o;
    o.x = tf32r(v.x); o.y = tf32r(v.y); o.z = tf32r(v.z); o.w = tf32r(v.w);
    ((float4*)dst)[i4] = o;
}

__global__ __launch_bounds__(256)
void round_all_kernel(const float* __restrict__ q, const float* __restrict__ k,
                      const float* __restrict__ v,
                      const float* __restrict__ wq, const float* __restrict__ wk,
                      const float* __restrict__ wv, const float* __restrict__ wo) {
    const int z = blockIdx.y;
    const size_t stride = (size_t)gridDim.x * blockDim.x;
    if (z < 3) {
        const float* src = (z == 0) ? q : (z == 1) ? k : v;
        float* dst = (z == 0) ? g_aq : (z == 1) ? g_ak : g_av;
        const size_t n4 = NELEM / 4;
        for (size_t i = (size_t)blockIdx.x * blockDim.x + threadIdx.x; i < n4; i += stride)
            round4(((const float4*)src)[i], dst, i);
    } else {
        const float* wsrc[4] = {wq, wk, wv, wo};
        const size_t w4 = WELEM / 4;                 // float4 per weight tensor
        const size_t n4 = 4 * w4;
        for (size_t i = (size_t)blockIdx.x * blockDim.x + threadIdx.x; i < n4; i += stride) {
            const int w = (int)(i / w4);
            const size_t off = i % w4;
            round4(((const float4*)wsrc[w])[off], g_w[w], off);
        }
    }
}

// ---------------- per-token head attention, 2x2 tiling, q direct-from-L1 ----------------
// 4 tokens per 256-thread block; 64 threads per token (hp = s64>>3, gp/cp = s64&7).
// k tile XOR-swizzled (slot c ^ (r>>1)); v natural; q rows read straight from g_q
// (8-lane broadcast LDG, L1-resident) -> smem/token 9.3KB -> 6 CTAs/SM.
__global__ __launch_bounds__(256)
void attn_kernel() {
    extern __shared__ float asmem[];
    const int t    = threadIdx.x;
    const int grp  = t >> 6;       // token slot in block
    const int s64  = t & 63;
    const int token = blockIdx.x * ATOK + grp;
    const int b = token >> 12;
    const int s = token & 4095;

    float* ks = asmem + grp * TOK_F;
    float* vs = ks + 1024;
    float* at = vs + 1024;         // [16][17]

    const size_t base = (size_t)token * 1024;
    const float4* gq = (const float4*)(g_q + base);
    {
        const float4* gk = (const float4*)(g_k + base);
        const float4* gv = (const float4*)(g_v + base);
#pragma unroll
        for (int i = 0; i < 4; i++) {
            const int slot = s64 + i * 64;           // 0..255
            const int r = slot >> 4, c = slot & 15;
            ((float4*)vs)[slot] = gv[slot];
            ((float4*)ks)[r * 16 + (c ^ ((r >> 1) & 7))] = gk[slot];
        }
    }
    __syncthreads();

    const int hp = s64 >> 3;       // 0..7
    const int gp = s64 & 7;        // 0..7

    // ---- score phase: 2x2 tile, d ascending; q from L1, k via XOR-swizzled smem ----
    {
        float a00 = 0.f, a01 = 0.f, a10 = 0.f, a11 = 0.f;
        const float4* k4 = (const float4*)ks;
#pragma unroll
        for (int j = 0; j < 16; j++) {
            const int js = j ^ gp;                 // swizzled col slot (r>>1 == gp)
            float4 q0 = gq[(2 * hp) * 16 + j];
            float4 q1 = gq[(2 * hp + 1) * 16 + j];
            float4 k0 = k4[(2 * gp) * 16 + js];
            float4 k1 = k4[(2 * gp + 1) * 16 + js];
            a00 += q0.x * k0.x + q0.y * k0.y + q0.z * k0.z + q0.w * k0.w;
            a01 += q0.x * k1.x + q0.y * k1.y + q0.z * k1.z + q0.w * k1.w;
            a10 += q1.x * k0.x + q1.y * k0.y + q1.z * k0.z + q1.w * k0.w;
            a11 += q1.x * k1.x + q1.y * k1.y + q1.z * k1.z + q1.w * k1.w;
        }
        at[(2 * hp) * 17 + 2 * gp]         = a00 * 0.125f;
        at[(2 * hp) * 17 + 2 * gp + 1]     = a01 * 0.125f;
        at[(2 * hp + 1) * 17 + 2 * gp]     = a10 * 0.125f;
        at[(2 * hp + 1) * 17 + 2 * gp + 1] = a11 * 0.125f;
    }
    __syncthreads();

    // ---- softmax: 16 threads per token, one row each ----
    if (s64 < 16) {
        float* row = at + s64 * 17;
        float mx = row[0];
#pragma unroll
        for (int j = 1; j < 16; j++) mx = fmaxf(mx, row[j]);
        float p[16];
        float sum = 0.f;
#pragma unroll
        for (int j = 0; j < 16; j++) { p[j] = __expf(row[j] - mx); sum += p[j]; }
        const float inv = 1.f / sum;
#pragma unroll
        for (int j = 0; j < 16; j++) row[j] = p[j] * inv;
    }
    __syncthreads();

    // ---- AV phase: rows {2hp,2hp+1}, float4-cols {cp, cp+8}, gg ascending ----
    const int cp = gp;
    float4 o00 = make_float4(0.f, 0.f, 0.f, 0.f), o01 = o00, o10 = o00, o11 = o00;
    const float4* v4 = (const float4*)vs;
#pragma unroll
    for (int gg = 0; gg < 16; gg++) {
        const float w0 = at[(2 * hp) * 17 + gg];
        const float w1 = at[(2 * hp + 1) * 17 + gg];
        const float4 va = v4[gg * 16 + cp];
        const float4 vb = v4[gg * 16 + cp + 8];
        o00.x += w0 * va.x; o00.y += w0 * va.y; o00.z += w0 * va.z; o00.w += w0 * va.w;
        o01.x += w0 * vb.x; o01.y += w0 * vb.y; o01.z += w0 * vb.z; o01.w += w0 * vb.w;
        o10.x += w1 * va.x; o10.y += w1 * va.y; o10.z += w1 * va.z; o10.w += w1 * va.w;
        o11.x += w1 * vb.x; o11.y += w1 * vb.y; o11.z += w1 * vb.z; o11.w += w1 * vb.w;
    }

    // scrambled layout + tf32 rounding (feeds the tf32 out-GEMM)
    const int scol = (s & 15) * 64;
    const int srow = s >> 4;
#pragma unroll
    for (int e = 0; e < 2; e++) {
        const int h2 = 2 * hp + e;
        const size_t row = (size_t)b * 4096 + (size_t)h2 * 256 + srow;
        float4 oa = e ? o10 : o00;
        float4 ob = e ? o11 : o01;
        float4 ra, rb;
        ra.x = tf32r(oa.x); ra.y = tf32r(oa.y); ra.z = tf32r(oa.z); ra.w = tf32r(oa.w);
        rb.x = tf32r(ob.x); rb.y = tf32r(ob.y); rb.z = tf32r(ob.z); rb.w = tf32r(ob.w);
        *(float4*)(g_x + row * 1024 + scol + cp * 4)       = ra;
        *(float4*)(g_x + row * 1024 + scol + (cp + 8) * 4) = rb;
    }
}

// ---------------- launch ----------------
extern "C" void kernel_launch(void* const* d_in, const int* in_sizes, int n_in,
                              void* d_out, int out_size) {
    (void)in_sizes; (void)n_in; (void)out_size;
    const float* query = (const float*)d_in[0];
    const float* key   = (const float*)d_in[1];
    const float* value = (const float*)d_in[2];
    const float* Wq = (const float*)d_in[3];
    const float* bq = (const float*)d_in[4];
    const float* Wk = (const float*)d_in[5];
    const float* bk = (const float*)d_in[6];
    const float* Wv = (const float*)d_in[7];
    const float* bv = (const float*)d_in[8];
    const float* Wo = (const float*)d_in[9];
    const float* bo = (const float*)d_in[10];
    float* out = (float*)d_out;

    cudaFuncSetAttribute(qkv_mma_kernel, cudaFuncAttributeMaxDynamicSharedMemorySize, SMEM_DYN);
    cudaFuncSetAttribute(out_mma_kernel, cudaFuncAttributeMaxDynamicSharedMemorySize, SMEM_DYN);
    cudaFuncSetAttribute(attn_kernel, cudaFuncAttributeMaxDynamicSharedMemorySize, ATTN_SMEM);

    round_all_kernel<<<dim3(4096, 4), 256>>>(query, key, value, Wq, Wk, Wv, Wo);
    qkv_mma_kernel<<<dim3(KD / TN, MDIM / TMC, 3), NTHR, SMEM_DYN>>>(bq, bk, bv);
    attn_kernel<<<MDIM / ATOK, 256, ATTN_SMEM>>>();
    out_mma_kernel<<<dim3(KD / TN, MDIM / TMC, 1), NTHR, SMEM_DYN>>>(bo, out);
}

// round 15
// speedup vs baseline: 1.6992x; 1.4970x over previous
#include <cuda_runtime.h>
#include <cuda_fp16.h>
#include <cstdint>

// ---------------- problem constants ----------------
#define MDIM 16384          // B*S
#define KD   1024           // d_model
#define NELEM ((size_t)MDIM * KD)
#define WELEM ((size_t)KD * KD)

// GEMM tiling: CTA 128x128, 8 warps (2x4), warp tile 64x32, BK=32 halfs (2 k16-steps)
// fp16 operands (same 10-bit mantissa as tf32), fp32 accumulate. 2 CTAs/SM.
#define TMC 128
#define TN  128
#define BK  32
#define NCH (KD / BK)                 // 32 chunks
#define PITCHB 80                     // smem row pitch bytes (64B data + 16B pad, conflict-free)
#define A_BYTES (128 * PITCHB)        // 10240
#define B_BYTES (128 * PITCHB)        // 10240
#define STAGE_BYTES (A_BYTES + B_BYTES)  // 20480
#define STAGES 3
#define SMEM_DYN (STAGES * STAGE_BYTES)  // 61440 (x2 CTAs = 122880 <= 227KB)
#define NTHR 256

// attn: 4 tokens per 256-thread block, 64 threads per token; q read direct from L1
#define ATOK 4
#define TOK_F 2320                     // floats per token: k1024 + v1024 + at(16*17)
#define ATTN_SMEM (ATOK * TOK_F * 4)   // 37120 bytes -> 6 CTAs/SM

// ---------------- device scratch ----------------
__device__ __half g_aq[NELEM], g_ak[NELEM], g_av[NELEM];  // fp16 activations
__device__ __half g_w[4][WELEM];                           // fp16 weights
__device__ float  g_q[NELEM], g_k[NELEM], g_v[NELEM];      // fp32 projections
__device__ __half g_x[NELEM];                              // attn out (fp16, scrambled)

// ---------------- PTX helpers ----------------
__device__ __forceinline__ uint32_t smem_u32(const void* p) {
    uint32_t a;
    asm("{ .reg .u64 t; cvta.to.shared.u64 t, %1; cvt.u32.u64 %0, t; }" : "=r"(a) : "l"(p));
    return a;
}
__device__ __forceinline__ void cp16(uint32_t dst, const void* src) {
    asm volatile("cp.async.cg.shared.global [%0], [%1], 16;" :: "r"(dst), "l"(src));
}
__device__ __forceinline__ void cp_commit() { asm volatile("cp.async.commit_group;"); }
__device__ __forceinline__ void ldm_x4(uint32_t r[4], uint32_t addr) {
    asm volatile("ldmatrix.sync.aligned.m8n8.x4.shared.b16 {%0,%1,%2,%3}, [%4];"
                 : "=r"(r[0]), "=r"(r[1]), "=r"(r[2]), "=r"(r[3]) : "r"(addr));
}
__device__ __forceinline__ void mma_f16(float c[4], const uint32_t a[4],
                                        uint32_t b0, uint32_t b1) {
    asm volatile(
        "mma.sync.aligned.m16n8k16.row.col.f32.f16.f16.f32 "
        "{%0,%1,%2,%3}, {%4,%5,%6,%7}, {%8,%9}, {%0,%1,%2,%3};"
        : "+f"(c[0]), "+f"(c[1]), "+f"(c[2]), "+f"(c[3])
        : "r"(a[0]), "r"(a[1]), "r"(a[2]), "r"(a[3]), "r"(b0), "r"(b1));
}

// ---------------- GEMM: C[16384,1024] = A*W^T + bias (fp16 single-pass) ----------------
// A: [MDIM, KD] fp16 row-major (2048 B/row). W: [KD(out), KD(in)] fp16 row-major.
__device__ __forceinline__ void f16_gemm_body(
    const __half* __restrict__ A, const __half* __restrict__ W,
    const float* __restrict__ bias, float* __restrict__ C)
{
    extern __shared__ char dynsm[];
    const uint32_t sb = smem_u32(dynsm);

    const int t    = threadIdx.x;
    const int lane = t & 31;
    const int wid  = t >> 5;
    const int wm   = (wid >> 2) * 64;    // warp m offset (0/64)
    const int wn   = (wid & 3) * 32;     // warp n offset (0..96)
    const int m0   = blockIdx.y * TMC;
    const int n0   = blockIdx.x * TN;

    const char* pA = (const char*)A;
    const char* pW = (const char*)W;

    float acc[4][4][4];
#pragma unroll
    for (int i = 0; i < 4; i++)
#pragma unroll
        for (int j = 0; j < 4; j++)
#pragma unroll
            for (int r = 0; r < 4; r++) acc[i][j][r] = 0.f;

    // cp.async slots: A = 512 x 16B (128 rows x 4 quarters), B = 512 x 16B
    const int sl[2] = {t, t + 256};

    auto load_chunk = [&](int c, int buf) {
        const uint32_t s  = sb + (uint32_t)buf * STAGE_BYTES;
        const uint32_t sB = s + A_BYTES;
        const size_t kb = (size_t)c * 64;            // 32 halfs = 64B per chunk-row
#pragma unroll
        for (int i = 0; i < 2; i++) {
            const int r = sl[i] >> 2, q = sl[i] & 3;
            const uint32_t off = (uint32_t)(r * PITCHB + q * 16);
            cp16(s  + off, pA + (size_t)(m0 + r) * 2048 + kb + q * 16);
            cp16(sB + off, pW + (size_t)(n0 + r) * 2048 + kb + q * 16);
        }
    };

    load_chunk(0, 0); cp_commit();
    load_chunk(1, 1); cp_commit();

    // ldmatrix lane address pieces (b16 fragments)
    // A x4: (m0-7,k0-7),(m8-15,k0-7),(m0-7,k8-15),(m8-15,k8-15)
    const uint32_t aBase = (uint32_t)((wm + (lane & 15)) * PITCHB + (lane >> 4) * 16);
    // B x4: (n0-7,k0-7),(n0-7,k8-15),(n8-15,k0-7),(n8-15,k8-15)
    const uint32_t bBase = (uint32_t)((wn + (lane & 7) + ((lane >> 4) << 3)) * PITCHB
                                      + ((lane >> 3) & 1) * 16);

#pragma unroll 1
    for (int c = 0; c < NCH; c++) {
        asm volatile("cp.async.wait_group 1;");
        __syncthreads();

        // issue next loads into the buffer consumed LAST iteration (safe post-sync)
        if (c + 2 < NCH) load_chunk(c + 2, (c + 2) % STAGES);
        cp_commit();

        const uint32_t s  = sb + (uint32_t)(c % STAGES) * STAGE_BYTES;
        const uint32_t sA = s;
        const uint32_t sB = s + A_BYTES;

#pragma unroll
        for (int ks = 0; ks < 2; ks++) {
            const uint32_t kb = (uint32_t)(ks * 32);   // 16 halfs = 32B per k16 step
            uint32_t af[4][4], bf[2][4];
#pragma unroll
            for (int mt = 0; mt < 4; mt++)
                ldm_x4(af[mt], sA + aBase + (uint32_t)(mt * 16 * PITCHB) + kb);
#pragma unroll
            for (int nn = 0; nn < 2; nn++)
                ldm_x4(bf[nn], sB + bBase + (uint32_t)(nn * 16 * PITCHB) + kb);
#pragma unroll
            for (int mt = 0; mt < 4; mt++) {
#pragma unroll
                for (int j = 0; j < 4; j++) {
                    const int p = j >> 1, e = (j & 1) * 2;
                    mma_f16(acc[mt][j], af[mt], bf[p][e], bf[p][e + 1]);
                }
            }
        }
    }

    // epilogue: bias + fp32 store
    const int tr = lane >> 2;
    const int tc = (lane & 3) * 2;
#pragma unroll
    for (int mt = 0; mt < 4; mt++) {
        const int gr = m0 + wm + mt * 16 + tr;
        float* row0 = C + (size_t)gr * KD + n0 + wn;
        float* row1 = row0 + 8 * KD;
#pragma unroll
        for (int j = 0; j < 4; j++) {
            const int gc = wn + j * 8 + tc;
            float2 bb = *(const float2*)(bias + n0 + gc);
            float2 o0, o1;
            o0.x = acc[mt][j][0] + bb.x;  o0.y = acc[mt][j][1] + bb.y;
            o1.x = acc[mt][j][2] + bb.x;  o1.y = acc[mt][j][3] + bb.y;
            *(float2*)(row0 + j * 8 + tc) = o0;
            *(float2*)(row1 + j * 8 + tc) = o1;
        }
    }
}

__global__ __launch_bounds__(NTHR, 2)
void qkv_mma_kernel(const float* __restrict__ bq, const float* __restrict__ bk,
                    const float* __restrict__ bv) {
    const int z = blockIdx.z;
    const __half* A = (z == 0) ? g_aq : (z == 1) ? g_ak : g_av;
    const float* bias = (z == 0) ? bq : (z == 1) ? bk : bv;
    float* C = (z == 0) ? g_q : (z == 1) ? g_k : g_v;
    f16_gemm_body(A, g_w[z], bias, C);
}

__global__ __launch_bounds__(NTHR, 2)
void out_mma_kernel(const float* __restrict__ bo, float* __restrict__ out) {
    f16_gemm_body(g_x, g_w[3], bo, out);
}

// ---------------- fp32 -> fp16 conversion: single fused pass (acts + weights) ----------------
__device__ __forceinline__ void cvt4_store(const float4 v, __half* dst, size_t i4) {
    __half2 lo = __floats2half2_rn(v.x, v.y);
    __half2 hi = __floats2half2_rn(v.z, v.w);
    uint2 o = make_uint2(*(uint32_t*)&lo, *(uint32_t*)&hi);
    ((uint2*)dst)[i4] = o;
}

__global__ __launch_bounds__(256)
void cvt_all_kernel(const float* __restrict__ q, const float* __restrict__ k,
                    const float* __restrict__ v,
                    const float* __restrict__ wq, const float* __restrict__ wk,
                    const float* __restrict__ wv, const float* __restrict__ wo) {
    const int z = blockIdx.y;
    const size_t stride = (size_t)gridDim.x * blockDim.x;
    if (z < 3) {
        const float* src = (z == 0) ? q : (z == 1) ? k : v;
        __half* dst = (z == 0) ? g_aq : (z == 1) ? g_ak : g_av;
        const size_t n4 = NELEM / 4;
        for (size_t i = (size_t)blockIdx.x * blockDim.x + threadIdx.x; i < n4; i += stride)
            cvt4_store(((const float4*)src)[i], dst, i);
    } else {
        const float* wsrc[4] = {wq, wk, wv, wo};
        const size_t w4 = WELEM / 4;
        const size_t n4 = 4 * w4;
        for (size_t i = (size_t)blockIdx.x * blockDim.x + threadIdx.x; i < n4; i += stride) {
            const int w = (int)(i / w4);
            const size_t off = i % w4;
            cvt4_store(((const float4*)wsrc[w])[off], g_w[w], off);
        }
    }
}

// ---------------- per-token head attention, 2x2 tiling, q direct-from-L1 ----------------
// 4 tokens per 256-thread block; 64 threads per token (hp = s64>>3, gp/cp = s64&7).
// k tile XOR-swizzled (slot c ^ (r>>1)); v natural; q rows read straight from g_q.
// Output written as fp16 into the scrambled layout feeding the out-GEMM.
__global__ __launch_bounds__(256)
void attn_kernel() {
    extern __shared__ float asmem[];
    const int t    = threadIdx.x;
    const int grp  = t >> 6;       // token slot in block
    const int s64  = t & 63;
    const int token = blockIdx.x * ATOK + grp;
    const int b = token >> 12;
    const int s = token & 4095;

    float* ks = asmem + grp * TOK_F;
    float* vs = ks + 1024;
    float* at = vs + 1024;         // [16][17]

    const size_t base = (size_t)token * 1024;
    const float4* gq = (const float4*)(g_q + base);
    {
        const float4* gk = (const float4*)(g_k + base);
        const float4* gv = (const float4*)(g_v + base);
#pragma unroll
        for (int i = 0; i < 4; i++) {
            const int slot = s64 + i * 64;           // 0..255
            const int r = slot >> 4, c = slot & 15;
            ((float4*)vs)[slot] = gv[slot];
            ((float4*)ks)[r * 16 + (c ^ ((r >> 1) & 7))] = gk[slot];
        }
    }
    __syncthreads();

    const int hp = s64 >> 3;       // 0..7
    const int gp = s64 & 7;        // 0..7

    // ---- score phase: 2x2 tile, d ascending; q from L1, k via XOR-swizzled smem ----
    {
        float a00 = 0.f, a01 = 0.f, a10 = 0.f, a11 = 0.f;
        const float4* k4 = (const float4*)ks;
#pragma unroll
        for (int j = 0; j < 16; j++) {
            const int js = j ^ gp;
            float4 q0 = gq[(2 * hp) * 16 + j];
            float4 q1 = gq[(2 * hp + 1) * 16 + j];
            float4 k0 = k4[(2 * gp) * 16 + js];
            float4 k1 = k4[(2 * gp + 1) * 16 + js];
            a00 += q0.x * k0.x + q0.y * k0.y + q0.z * k0.z + q0.w * k0.w;
            a01 += q0.x * k1.x + q0.y * k1.y + q0.z * k1.z + q0.w * k1.w;
            a10 += q1.x * k0.x + q1.y * k0.y + q1.z * k0.z + q1.w * k0.w;
            a11 += q1.x * k1.x + q1.y * k1.y + q1.z * k1.z + q1.w * k1.w;
        }
        at[(2 * hp) * 17 + 2 * gp]         = a00 * 0.125f;
        at[(2 * hp) * 17 + 2 * gp + 1]     = a01 * 0.125f;
        at[(2 * hp + 1) * 17 + 2 * gp]     = a10 * 0.125f;
        at[(2 * hp + 1) * 17 + 2 * gp + 1] = a11 * 0.125f;
    }
    __syncthreads();

    // ---- softmax: 16 threads per token, one row each ----
    if (s64 < 16) {
        float* row = at + s64 * 17;
        float mx = row[0];
#pragma unroll
        for (int j = 1; j < 16; j++) mx = fmaxf(mx, row[j]);
        float p[16];
        float sum = 0.f;
#pragma unroll
        for (int j = 0; j < 16; j++) { p[j] = __expf(row[j] - mx); sum += p[j]; }
        const float inv = 1.f / sum;
#pragma unroll
        for (int j = 0; j < 16; j++) row[j] = p[j] * inv;
    }
    __syncthreads();

    // ---- AV phase: rows {2hp,2hp+1}, float4-cols {cp, cp+8}, gg ascending ----
    const int cp = gp;
    float4 o00 = make_float4(0.f, 0.f, 0.f, 0.f), o01 = o00, o10 = o00, o11 = o00;
    const float4* v4 = (const float4*)vs;
#pragma unroll
    for (int gg = 0; gg < 16; gg++) {
        const float w0 = at[(2 * hp) * 17 + gg];
        const float w1 = at[(2 * hp + 1) * 17 + gg];
        const float4 va = v4[gg * 16 + cp];
        const float4 vb = v4[gg * 16 + cp + 8];
        o00.x += w0 * va.x; o00.y += w0 * va.y; o00.z += w0 * va.z; o00.w += w0 * va.w;
        o01.x += w0 * vb.x; o01.y += w0 * vb.y; o01.z += w0 * vb.z; o01.w += w0 * vb.w;
        o10.x += w1 * va.x; o10.y += w1 * va.y; o10.z += w1 * va.z; o10.w += w1 * va.w;
        o11.x += w1 * vb.x; o11.y += w1 * vb.y; o11.z += w1 * vb.z; o11.w += w1 * vb.w;
    }

    // scrambled layout, fp16 (feeds the fp16 out-GEMM)
    const int scol = (s & 15) * 64;
    const int srow = s >> 4;
#pragma unroll
    for (int e = 0; e < 2; e++) {
        const int h2 = 2 * hp + e;
        const size_t row = (size_t)b * 4096 + (size_t)h2 * 256 + srow;
        float4 oa = e ? o10 : o00;
        float4 ob = e ? o11 : o01;
        __half2 a0 = __floats2half2_rn(oa.x, oa.y);
        __half2 a1 = __floats2half2_rn(oa.z, oa.w);
        __half2 b0 = __floats2half2_rn(ob.x, ob.y);
        __half2 b1 = __floats2half2_rn(ob.z, ob.w);
        const size_t idx = row * 1024 + scol;
        *(uint2*)(g_x + idx + cp * 4)       = make_uint2(*(uint32_t*)&a0, *(uint32_t*)&a1);
        *(uint2*)(g_x + idx + (cp + 8) * 4) = make_uint2(*(uint32_t*)&b0, *(uint32_t*)&b1);
    }
}

// ---------------- launch ----------------
extern "C" void kernel_launch(void* const* d_in, const int* in_sizes, int n_in,
                              void* d_out, int out_size) {
    (void)in_sizes; (void)n_in; (void)out_size;
    const float* query = (const float*)d_in[0];
    const float* key   = (const float*)d_in[1];
    const float* value = (const float*)d_in[2];
    const float* Wq = (const float*)d_in[3];
    const float* bq = (const float*)d_in[4];
    const float* Wk = (const float*)d_in[5];
    const float* bk = (const float*)d_in[6];
    const float* Wv = (const float*)d_in[7];
    const float* bv = (const float*)d_in[8];
    const float* Wo = (const float*)d_in[9];
    const float* bo = (const float*)d_in[10];
    float* out = (float*)d_out;

    cudaFuncSetAttribute(qkv_mma_kernel, cudaFuncAttributeMaxDynamicSharedMemorySize, SMEM_DYN);
    cudaFuncSetAttribute(out_mma_kernel, cudaFuncAttributeMaxDynamicSharedMemorySize, SMEM_DYN);
    cudaFuncSetAttribute(attn_kernel, cudaFuncAttributeMaxDynamicSharedMemorySize, ATTN_SMEM);

    cvt_all_kernel<<<dim3(4096, 4), 256>>>(query, key, value, Wq, Wk, Wv, Wo);
    qkv_mma_kernel<<<dim3(KD / TN, MDIM / TMC, 3), NTHR, SMEM_DYN>>>(bq, bk, bv);
    attn_kernel<<<MDIM / ATOK, 256, ATTN_SMEM>>>();
    out_mma_kernel<<<dim3(KD / TN, MDIM / TMC, 1), NTHR, SMEM_DYN>>>(bo, out);
}

// round 16
// speedup vs baseline: 1.9313x; 1.1366x over previous
#include <cuda_runtime.h>
#include <cuda_fp16.h>
#include <cstdint>

// ---------------- problem constants ----------------
#define MDIM 16384          // B*S
#define KD   1024           // d_model
#define NELEM ((size_t)MDIM * KD)
#define WELEM ((size_t)KD * KD)

// GEMM tiling: CTA 128x128, 8 warps (2x4), warp tile 64x32, BK=64 halfs (4 k16-steps)
// fp16 operands, fp32 accumulate. 2 CTAs/SM, 3-stage single-sync pipeline.
#define TMC 128
#define TN  128
#define BK  64
#define NCH (KD / BK)                 // 16 chunks
#define PITCHB 144                    // smem row pitch bytes (128B data + 16B pad)
#define A_BYTES (128 * PITCHB)        // 18432
#define B_BYTES (128 * PITCHB)        // 18432
#define STAGE_BYTES (A_BYTES + B_BYTES)  // 36864
#define STAGES 3
#define SMEM_DYN (STAGES * STAGE_BYTES)  // 110592 (x2 CTAs = 221184 <= 227KB)
#define NTHR 256

// attn: 4 tokens per 256-thread block, 64 threads per token; q read direct from L1
#define ATOK 4
#define TOK_F 2320                     // floats per token: k1024 + v1024 + at(16*17)
#define ATTN_SMEM (ATOK * TOK_F * 4)   // 37120 bytes -> 6 CTAs/SM

// ---------------- device scratch ----------------
__device__ __half g_aq[NELEM], g_ak[NELEM], g_av[NELEM];  // fp16 activations
__device__ __half g_w[4][WELEM];                           // fp16 weights
__device__ float  g_q[NELEM], g_k[NELEM], g_v[NELEM];      // fp32 projections
__device__ __half g_x[NELEM];                              // attn out (fp16, scrambled)

// ---------------- PTX helpers ----------------
__device__ __forceinline__ uint32_t smem_u32(const void* p) {
    uint32_t a;
    asm("{ .reg .u64 t; cvta.to.shared.u64 t, %1; cvt.u32.u64 %0, t; }" : "=r"(a) : "l"(p));
    return a;
}
__device__ __forceinline__ void cp16(uint32_t dst, const void* src) {
    asm volatile("cp.async.cg.shared.global [%0], [%1], 16;" :: "r"(dst), "l"(src));
}
__device__ __forceinline__ void cp_commit() { asm volatile("cp.async.commit_group;"); }
__device__ __forceinline__ void ldm_x4(uint32_t r[4], uint32_t addr) {
    asm volatile("ldmatrix.sync.aligned.m8n8.x4.shared.b16 {%0,%1,%2,%3}, [%4];"
                 : "=r"(r[0]), "=r"(r[1]), "=r"(r[2]), "=r"(r[3]) : "r"(addr));
}
__device__ __forceinline__ void mma_f16(float c[4], const uint32_t a[4],
                                        uint32_t b0, uint32_t b1) {
    asm volatile(
        "mma.sync.aligned.m16n8k16.row.col.f32.f16.f16.f32 "
        "{%0,%1,%2,%3}, {%4,%5,%6,%7}, {%8,%9}, {%0,%1,%2,%3};"
        : "+f"(c[0]), "+f"(c[1]), "+f"(c[2]), "+f"(c[3])
        : "r"(a[0]), "r"(a[1]), "r"(a[2]), "r"(a[3]), "r"(b0), "r"(b1));
}

// ---------------- GEMM: C[16384,1024] = A*W^T + bias (fp16 single-pass) ----------------
// A: [MDIM, KD] fp16 row-major (2048 B/row). W: [KD(out), KD(in)] fp16 row-major.
__device__ __forceinline__ void f16_gemm_body(
    const __half* __restrict__ A, const __half* __restrict__ W,
    const float* __restrict__ bias, float* __restrict__ C)
{
    extern __shared__ char dynsm[];
    const uint32_t sb = smem_u32(dynsm);

    const int t    = threadIdx.x;
    const int lane = t & 31;
    const int wid  = t >> 5;
    const int wm   = (wid >> 2) * 64;    // warp m offset (0/64)
    const int wn   = (wid & 3) * 32;     // warp n offset (0..96)
    const int m0   = blockIdx.y * TMC;
    const int n0   = blockIdx.x * TN;

    const char* pA = (const char*)A;
    const char* pW = (const char*)W;

    float acc[4][4][4];
#pragma unroll
    for (int i = 0; i < 4; i++)
#pragma unroll
        for (int j = 0; j < 4; j++)
#pragma unroll
            for (int r = 0; r < 4; r++) acc[i][j][r] = 0.f;

    // cp.async slots: A = 1024 x 16B (128 rows x 8 eighths), B = 1024 x 16B
    const int sl[4] = {t, t + 256, t + 512, t + 768};

    auto load_chunk = [&](int c, int buf) {
        const uint32_t s  = sb + (uint32_t)buf * STAGE_BYTES;
        const uint32_t sB = s + A_BYTES;
        const size_t kb = (size_t)c * 128;           // 64 halfs = 128B per chunk-row
#pragma unroll
        for (int i = 0; i < 4; i++) {
            const int r = sl[i] >> 3, q = sl[i] & 7;
            const uint32_t off = (uint32_t)(r * PITCHB + q * 16);
            cp16(s  + off, pA + (size_t)(m0 + r) * 2048 + kb + q * 16);
            cp16(sB + off, pW + (size_t)(n0 + r) * 2048 + kb + q * 16);
        }
    };

    load_chunk(0, 0); cp_commit();
    load_chunk(1, 1); cp_commit();

    // ldmatrix lane address pieces (b16 fragments)
    // A x4: (m0-7,k0-7),(m8-15,k0-7),(m0-7,k8-15),(m8-15,k8-15)
    const uint32_t aBase = (uint32_t)((wm + (lane & 15)) * PITCHB + (lane >> 4) * 16);
    // B x4: (n0-7,k0-7),(n0-7,k8-15),(n8-15,k0-7),(n8-15,k8-15)
    const uint32_t bBase = (uint32_t)((wn + (lane & 7) + ((lane >> 4) << 3)) * PITCHB
                                      + ((lane >> 3) & 1) * 16);

#pragma unroll 1
    for (int c = 0; c < NCH; c++) {
        asm volatile("cp.async.wait_group 1;");
        __syncthreads();

        // issue next loads into the buffer consumed LAST iteration (safe post-sync)
        if (c + 2 < NCH) load_chunk(c + 2, (c + 2) % STAGES);
        cp_commit();

        const uint32_t s  = sb + (uint32_t)(c % STAGES) * STAGE_BYTES;
        const uint32_t sA = s;
        const uint32_t sB = s + A_BYTES;

#pragma unroll
        for (int ks = 0; ks < 4; ks++) {
            const uint32_t kb = (uint32_t)(ks * 32);   // 16 halfs = 32B per k16 step
            uint32_t af[4][4], bf[2][4];
#pragma unroll
            for (int mt = 0; mt < 4; mt++)
                ldm_x4(af[mt], sA + aBase + (uint32_t)(mt * 16 * PITCHB) + kb);
#pragma unroll
            for (int nn = 0; nn < 2; nn++)
                ldm_x4(bf[nn], sB + bBase + (uint32_t)(nn * 16 * PITCHB) + kb);
#pragma unroll
            for (int mt = 0; mt < 4; mt++) {
#pragma unroll
                for (int j = 0; j < 4; j++) {
                    const int p = j >> 1, e = (j & 1) * 2;
                    mma_f16(acc[mt][j], af[mt], bf[p][e], bf[p][e + 1]);
                }
            }
        }
    }

    // epilogue: bias + fp32 store
    const int tr = lane >> 2;
    const int tc = (lane & 3) * 2;
#pragma unroll
    for (int mt = 0; mt < 4; mt++) {
        const int gr = m0 + wm + mt * 16 + tr;
        float* row0 = C + (size_t)gr * KD + n0 + wn;
        float* row1 = row0 + 8 * KD;
#pragma unroll
        for (int j = 0; j < 4; j++) {
            const int gc = wn + j * 8 + tc;
            float2 bb = *(const float2*)(bias + n0 + gc);
            float2 o0, o1;
            o0.x = acc[mt][j][0] + bb.x;  o0.y = acc[mt][j][1] + bb.y;
            o1.x = acc[mt][j][2] + bb.x;  o1.y = acc[mt][j][3] + bb.y;
            *(float2*)(row0 + j * 8 + tc) = o0;
            *(float2*)(row1 + j * 8 + tc) = o1;
        }
    }
}

__global__ __launch_bounds__(NTHR, 2)
void qkv_mma_kernel(const float* __restrict__ bq, const float* __restrict__ bk,
                    const float* __restrict__ bv) {
    const int z = blockIdx.z;
    const __half* A = (z == 0) ? g_aq : (z == 1) ? g_ak : g_av;
    const float* bias = (z == 0) ? bq : (z == 1) ? bk : bv;
    float* C = (z == 0) ? g_q : (z == 1) ? g_k : g_v;
    f16_gemm_body(A, g_w[z], bias, C);
}

__global__ __launch_bounds__(NTHR, 2)
void out_mma_kernel(const float* __restrict__ bo, float* __restrict__ out) {
    f16_gemm_body(g_x, g_w[3], bo, out);
}

// ---------------- fp32 -> fp16 conversion: single fused pass (acts + weights) ----------------
__device__ __forceinline__ void cvt4_store(const float4 v, __half* dst, size_t i4) {
    __half2 lo = __floats2half2_rn(v.x, v.y);
    __half2 hi = __floats2half2_rn(v.z, v.w);
    uint2 o = make_uint2(*(uint32_t*)&lo, *(uint32_t*)&hi);
    ((uint2*)dst)[i4] = o;
}

__global__ __launch_bounds__(256)
void cvt_all_kernel(const float* __restrict__ q, const float* __restrict__ k,
                    const float* __restrict__ v,
                    const float* __restrict__ wq, const float* __restrict__ wk,
                    const float* __restrict__ wv, const float* __restrict__ wo) {
    const int z = blockIdx.y;
    const size_t stride = (size_t)gridDim.x * blockDim.x;
    if (z < 3) {
        const float* src = (z == 0) ? q : (z == 1) ? k : v;
        __half* dst = (z == 0) ? g_aq : (z == 1) ? g_ak : g_av;
        const size_t n4 = NELEM / 4;
        for (size_t i = (size_t)blockIdx.x * blockDim.x + threadIdx.x; i < n4; i += stride)
            cvt4_store(((const float4*)src)[i], dst, i);
    } else {
        const float* wsrc[4] = {wq, wk, wv, wo};
        const size_t w4 = WELEM / 4;
        const size_t n4 = 4 * w4;
        for (size_t i = (size_t)blockIdx.x * blockDim.x + threadIdx.x; i < n4; i += stride) {
            const int w = (int)(i / w4);
            const size_t off = i % w4;
            cvt4_store(((const float4*)wsrc[w])[off], g_w[w], off);
        }
    }
}

// ---------------- per-token head attention, 2x2 tiling, q direct-from-L1 ----------------
// 4 tokens per 256-thread block; 64 threads per token (hp = s64>>3, gp/cp = s64&7).
// k tile XOR-swizzled (slot c ^ (r>>1)); v natural; q rows read straight from g_q.
// Output written as fp16 into the scrambled layout feeding the out-GEMM.
__global__ __launch_bounds__(256)
void attn_kernel() {
    extern __shared__ float asmem[];
    const int t    = threadIdx.x;
    const int grp  = t >> 6;       // token slot in block
    const int s64  = t & 63;
    const int token = blockIdx.x * ATOK + grp;
    const int b = token >> 12;
    const int s = token & 4095;

    float* ks = asmem + grp * TOK_F;
    float* vs = ks + 1024;
    float* at = vs + 1024;         // [16][17]

    const size_t base = (size_t)token * 1024;
    const float4* gq = (const float4*)(g_q + base);
    {
        const float4* gk = (const float4*)(g_k + base);
        const float4* gv = (const float4*)(g_v + base);
#pragma unroll
        for (int i = 0; i < 4; i++) {
            const int slot = s64 + i * 64;           // 0..255
            const int r = slot >> 4, c = slot & 15;
            ((float4*)vs)[slot] = gv[slot];
            ((float4*)ks)[r * 16 + (c ^ ((r >> 1) & 7))] = gk[slot];
        }
    }
    __syncthreads();

    const int hp = s64 >> 3;       // 0..7
    const int gp = s64 & 7;        // 0..7

    // ---- score phase: 2x2 tile, d ascending; q from L1, k via XOR-swizzled smem ----
    {
        float a00 = 0.f, a01 = 0.f, a10 = 0.f, a11 = 0.f;
        const float4* k4 = (const float4*)ks;
#pragma unroll
        for (int j = 0; j < 16; j++) {
            const int js = j ^ gp;
            float4 q0 = gq[(2 * hp) * 16 + j];
            float4 q1 = gq[(2 * hp + 1) * 16 + j];
            float4 k0 = k4[(2 * gp) * 16 + js];
            float4 k1 = k4[(2 * gp + 1) * 16 + js];
            a00 += q0.x * k0.x + q0.y * k0.y + q0.z * k0.z + q0.w * k0.w;
            a01 += q0.x * k1.x + q0.y * k1.y + q0.z * k1.z + q0.w * k1.w;
            a10 += q1.x * k0.x + q1.y * k0.y + q1.z * k0.z + q1.w * k0.w;
            a11 += q1.x * k1.x + q1.y * k1.y + q1.z * k1.z + q1.w * k1.w;
        }
        at[(2 * hp) * 17 + 2 * gp]         = a00 * 0.125f;
        at[(2 * hp) * 17 + 2 * gp + 1]     = a01 * 0.125f;
        at[(2 * hp + 1) * 17 + 2 * gp]     = a10 * 0.125f;
        at[(2 * hp + 1) * 17 + 2 * gp + 1] = a11 * 0.125f;
    }
    __syncthreads();

    // ---- softmax: 16 threads per token, one row each ----
    if (s64 < 16) {
        float* row = at + s64 * 17;
        float mx = row[0];
#pragma unroll
        for (int j = 1; j < 16; j++) mx = fmaxf(mx, row[j]);
        float p[16];
        float sum = 0.f;
#pragma unroll
        for (int j = 0; j < 16; j++) { p[j] = __expf(row[j] - mx); sum += p[j]; }
        const float inv = 1.f / sum;
#pragma unroll
        for (int j = 0; j < 16; j++) row[j] = p[j] * inv;
    }
    __syncthreads();

    // ---- AV phase: rows {2hp,2hp+1}, float4-cols {cp, cp+8}, gg ascending ----
    const int cp = gp;
    float4 o00 = make_float4(0.f, 0.f, 0.f, 0.f), o01 = o00, o10 = o00, o11 = o00;
    const float4* v4 = (const float4*)vs;
#pragma unroll
    for (int gg = 0; gg < 16; gg++) {
        const float w0 = at[(2 * hp) * 17 + gg];
        const float w1 = at[(2 * hp + 1) * 17 + gg];
        const float4 va = v4[gg * 16 + cp];
        const float4 vb = v4[gg * 16 + cp + 8];
        o00.x += w0 * va.x; o00.y += w0 * va.y; o00.z += w0 * va.z; o00.w += w0 * va.w;
        o01.x += w0 * vb.x; o01.y += w0 * vb.y; o01.z += w0 * vb.z; o01.w += w0 * vb.w;
        o10.x += w1 * va.x; o10.y += w1 * va.y; o10.z += w1 * va.z; o10.w += w1 * va.w;
        o11.x += w1 * vb.x; o11.y += w1 * vb.y; o11.z += w1 * vb.z; o11.w += w1 * vb.w;
    }

    // scrambled layout, fp16 (feeds the fp16 out-GEMM)
    const int scol = (s & 15) * 64;
    const int srow = s >> 4;
#pragma unroll
    for (int e = 0; e < 2; e++) {
        const int h2 = 2 * hp + e;
        const size_t row = (size_t)b * 4096 + (size_t)h2 * 256 + srow;
        float4 oa = e ? o10 : o00;
        float4 ob = e ? o11 : o01;
        __half2 a0 = __floats2half2_rn(oa.x, oa.y);
        __half2 a1 = __floats2half2_rn(oa.z, oa.w);
        __half2 b0 = __floats2half2_rn(ob.x, ob.y);
        __half2 b1 = __floats2half2_rn(ob.z, ob.w);
        const size_t idx = row * 1024 + scol;
        *(uint2*)(g_x + idx + cp * 4)       = make_uint2(*(uint32_t*)&a0, *(uint32_t*)&a1);
        *(uint2*)(g_x + idx + (cp + 8) * 4) = make_uint2(*(uint32_t*)&b0, *(uint32_t*)&b1);
    }
}

// ---------------- launch ----------------
extern "C" void kernel_launch(void* const* d_in, const int* in_sizes, int n_in,
                              void* d_out, int out_size) {
    (void)in_sizes; (void)n_in; (void)out_size;
    const float* query = (const float*)d_in[0];
    const float* key   = (const float*)d_in[1];
    const float* value = (const float*)d_in[2];
    const float* Wq = (const float*)d_in[3];
    const float* bq = (const float*)d_in[4];
    const float* Wk = (const float*)d_in[5];
    const float* bk = (const float*)d_in[6];
    const float* Wv = (const float*)d_in[7];
    const float* bv = (const float*)d_in[8];
    const float* Wo = (const float*)d_in[9];
    const float* bo = (const float*)d_in[10];
    float* out = (float*)d_out;

    cudaFuncSetAttribute(qkv_mma_kernel, cudaFuncAttributeMaxDynamicSharedMemorySize, SMEM_DYN);
    cudaFuncSetAttribute(out_mma_kernel, cudaFuncAttributeMaxDynamicSharedMemorySize, SMEM_DYN);
    cudaFuncSetAttribute(attn_kernel, cudaFuncAttributeMaxDynamicSharedMemorySize, ATTN_SMEM);

    cvt_all_kernel<<<dim3(4096, 4), 256>>>(query, key, value, Wq, Wk, Wv, Wo);
    qkv_mma_kernel<<<dim3(KD / TN, MDIM / TMC, 3), NTHR, SMEM_DYN>>>(bq, bk, bv);
    attn_kernel<<<MDIM / ATOK, 256, ATTN_SMEM>>>();
    out_mma_kernel<<<dim3(KD / TN, MDIM / TMC, 1), NTHR, SMEM_DYN>>>(bo, out);
}

// round 17
// speedup vs baseline: 1.9682x; 1.0191x over previous
#include <cuda_runtime.h>
#include <cuda_fp16.h>
#include <cstdint>

// ---------------- problem constants ----------------
#define MDIM 16384          // B*S
#define KD   1024           // d_model
#define NELEM ((size_t)MDIM * KD)
#define WELEM ((size_t)KD * KD)

// GEMM tiling: CTA 128x128, 8 warps (2x4), warp tile 64x32, BK=64 halfs (4 k16-steps)
// fp16 operands, fp32 accumulate. 2 CTAs/SM, 3-stage single-sync pipeline.
#define TMC 128
#define TN  128
#define BK  64
#define NCH (KD / BK)                 // 16 chunks
#define PITCHB 144                    // smem row pitch bytes (128B data + 16B pad)
#define A_BYTES (128 * PITCHB)        // 18432
#define B_BYTES (128 * PITCHB)        // 18432
#define STAGE_BYTES (A_BYTES + B_BYTES)  // 36864
#define STAGES 3
#define SMEM_DYN (STAGES * STAGE_BYTES)  // 110592 (x2 CTAs = 221184 <= 227KB)
#define NTHR 256

// attn: 4 tokens per 256-thread block, 64 threads per token; q direct from L1 (fp16)
#define ATOK 4
#define TOK_F 2320                     // floats per token: k1024 + v1024 + at(16*17)
#define ATTN_SMEM (ATOK * TOK_F * 4)   // 37120 bytes -> 6 CTAs/SM

// ---------------- device scratch ----------------
__device__ __half g_aq[NELEM], g_ak[NELEM], g_av[NELEM];  // fp16 activations
__device__ __half g_w[4][WELEM];                           // fp16 weights
__device__ __half g_q[NELEM], g_k[NELEM], g_v[NELEM];      // fp16 projections
__device__ __half g_x[NELEM];                              // attn out (fp16, scrambled)

// ---------------- PTX helpers ----------------
__device__ __forceinline__ uint32_t smem_u32(const void* p) {
    uint32_t a;
    asm("{ .reg .u64 t; cvta.to.shared.u64 t, %1; cvt.u32.u64 %0, t; }" : "=r"(a) : "l"(p));
    return a;
}
__device__ __forceinline__ void cp16(uint32_t dst, const void* src) {
    asm volatile("cp.async.cg.shared.global [%0], [%1], 16;" :: "r"(dst), "l"(src));
}
__device__ __forceinline__ void cp_commit() { asm volatile("cp.async.commit_group;"); }
__device__ __forceinline__ void ldm_x4(uint32_t r[4], uint32_t addr) {
    asm volatile("ldmatrix.sync.aligned.m8n8.x4.shared.b16 {%0,%1,%2,%3}, [%4];"
                 : "=r"(r[0]), "=r"(r[1]), "=r"(r[2]), "=r"(r[3]) : "r"(addr));
}
__device__ __forceinline__ void mma_f16(float c[4], const uint32_t a[4],
                                        uint32_t b0, uint32_t b1) {
    asm volatile(
        "mma.sync.aligned.m16n8k16.row.col.f32.f16.f16.f32 "
        "{%0,%1,%2,%3}, {%4,%5,%6,%7}, {%8,%9}, {%0,%1,%2,%3};"
        : "+f"(c[0]), "+f"(c[1]), "+f"(c[2]), "+f"(c[3])
        : "r"(a[0]), "r"(a[1]), "r"(a[2]), "r"(a[3]), "r"(b0), "r"(b1));
}
// fp16x4 (uint2) -> float4
__device__ __forceinline__ float4 h4_to_f4(uint2 h) {
    __half2 lo = *(__half2*)&h.x;
    __half2 hi = *(__half2*)&h.y;
    float2 f0 = __half22float2(lo);
    float2 f1 = __half22float2(hi);
    return make_float4(f0.x, f0.y, f1.x, f1.y);
}

// ---------------- GEMM: C[16384,1024] = A*W^T + bias (fp16 single-pass) ----------------
// A: [MDIM, KD] fp16 row-major (2048 B/row). W: [KD(out), KD(in)] fp16 row-major.
// F16OUT: write C as fp16 (q/k/v) vs fp32 (final out).
template <bool F16OUT>
__device__ __forceinline__ void f16_gemm_body(
    const __half* __restrict__ A, const __half* __restrict__ W,
    const float* __restrict__ bias, void* __restrict__ Cv)
{
    extern __shared__ char dynsm[];
    const uint32_t sb = smem_u32(dynsm);

    const int t    = threadIdx.x;
    const int lane = t & 31;
    const int wid  = t >> 5;
    const int wm   = (wid >> 2) * 64;    // warp m offset (0/64)
    const int wn   = (wid & 3) * 32;     // warp n offset (0..96)
    const int m0   = blockIdx.y * TMC;
    const int n0   = blockIdx.x * TN;

    const char* pA = (const char*)A;
    const char* pW = (const char*)W;

    float acc[4][4][4];
#pragma unroll
    for (int i = 0; i < 4; i++)
#pragma unroll
        for (int j = 0; j < 4; j++)
#pragma unroll
            for (int r = 0; r < 4; r++) acc[i][j][r] = 0.f;

    // cp.async slots: A = 1024 x 16B (128 rows x 8 eighths), B = 1024 x 16B
    const int sl[4] = {t, t + 256, t + 512, t + 768};

    auto load_chunk = [&](int c, int buf) {
        const uint32_t s  = sb + (uint32_t)buf * STAGE_BYTES;
        const uint32_t sB = s + A_BYTES;
        const size_t kb = (size_t)c * 128;           // 64 halfs = 128B per chunk-row
#pragma unroll
        for (int i = 0; i < 4; i++) {
            const int r = sl[i] >> 3, q = sl[i] & 7;
            const uint32_t off = (uint32_t)(r * PITCHB + q * 16);
            cp16(s  + off, pA + (size_t)(m0 + r) * 2048 + kb + q * 16);
            cp16(sB + off, pW + (size_t)(n0 + r) * 2048 + kb + q * 16);
        }
    };

    load_chunk(0, 0); cp_commit();
    load_chunk(1, 1); cp_commit();

    // ldmatrix lane address pieces (b16 fragments)
    const uint32_t aBase = (uint32_t)((wm + (lane & 15)) * PITCHB + (lane >> 4) * 16);
    const uint32_t bBase = (uint32_t)((wn + (lane & 7) + ((lane >> 4) << 3)) * PITCHB
                                      + ((lane >> 3) & 1) * 16);

#pragma unroll 1
    for (int c = 0; c < NCH; c++) {
        asm volatile("cp.async.wait_group 1;");
        __syncthreads();

        // issue next loads into the buffer consumed LAST iteration (safe post-sync)
        if (c + 2 < NCH) load_chunk(c + 2, (c + 2) % STAGES);
        cp_commit();

        const uint32_t s  = sb + (uint32_t)(c % STAGES) * STAGE_BYTES;
        const uint32_t sA = s;
        const uint32_t sB = s + A_BYTES;

#pragma unroll
        for (int ks = 0; ks < 4; ks++) {
            const uint32_t kb = (uint32_t)(ks * 32);   // 16 halfs = 32B per k16 step
            uint32_t af[4][4], bf[2][4];
#pragma unroll
            for (int mt = 0; mt < 4; mt++)
                ldm_x4(af[mt], sA + aBase + (uint32_t)(mt * 16 * PITCHB) + kb);
#pragma unroll
            for (int nn = 0; nn < 2; nn++)
                ldm_x4(bf[nn], sB + bBase + (uint32_t)(nn * 16 * PITCHB) + kb);
#pragma unroll
            for (int mt = 0; mt < 4; mt++) {
#pragma unroll
                for (int j = 0; j < 4; j++) {
                    const int p = j >> 1, e = (j & 1) * 2;
                    mma_f16(acc[mt][j], af[mt], bf[p][e], bf[p][e + 1]);
                }
            }
        }
    }

    // epilogue: bias + store (fp16 or fp32)
    const int tr = lane >> 2;
    const int tc = (lane & 3) * 2;
#pragma unroll
    for (int mt = 0; mt < 4; mt++) {
        const int gr = m0 + wm + mt * 16 + tr;
#pragma unroll
        for (int j = 0; j < 4; j++) {
            const int gc = wn + j * 8 + tc;
            float2 bb = *(const float2*)(bias + n0 + gc);
            float2 o0, o1;
            o0.x = acc[mt][j][0] + bb.x;  o0.y = acc[mt][j][1] + bb.y;
            o1.x = acc[mt][j][2] + bb.x;  o1.y = acc[mt][j][3] + bb.y;
            if (F16OUT) {
                __half* C = (__half*)Cv;
                __half* row0 = C + (size_t)gr * KD + n0 + gc;
                __half* row1 = row0 + 8 * KD;
                __half2 h0 = __floats2half2_rn(o0.x, o0.y);
                __half2 h1 = __floats2half2_rn(o1.x, o1.y);
                *(uint32_t*)row0 = *(uint32_t*)&h0;
                *(uint32_t*)row1 = *(uint32_t*)&h1;
            } else {
                float* C = (float*)Cv;
                float* row0 = C + (size_t)gr * KD + n0 + gc;
                float* row1 = row0 + 8 * KD;
                *(float2*)row0 = o0;
                *(float2*)row1 = o1;
            }
        }
    }
}

__global__ __launch_bounds__(NTHR, 2)
void qkv_mma_kernel(const float* __restrict__ bq, const float* __restrict__ bk,
                    const float* __restrict__ bv) {
    const int z = blockIdx.z;
    const __half* A = (z == 0) ? g_aq : (z == 1) ? g_ak : g_av;
    const float* bias = (z == 0) ? bq : (z == 1) ? bk : bv;
    __half* C = (z == 0) ? g_q : (z == 1) ? g_k : g_v;
    f16_gemm_body<true>(A, g_w[z], bias, C);
}

__global__ __launch_bounds__(NTHR, 2)
void out_mma_kernel(const float* __restrict__ bo, float* __restrict__ out) {
    f16_gemm_body<false>(g_x, g_w[3], bo, out);
}

// ---------------- fp32 -> fp16 conversion: single fused pass (acts + weights) ----------------
__device__ __forceinline__ void cvt4_store(const float4 v, __half* dst, size_t i4) {
    __half2 lo = __floats2half2_rn(v.x, v.y);
    __half2 hi = __floats2half2_rn(v.z, v.w);
    uint2 o = make_uint2(*(uint32_t*)&lo, *(uint32_t*)&hi);
    ((uint2*)dst)[i4] = o;
}

__global__ __launch_bounds__(256)
void cvt_all_kernel(const float* __restrict__ q, const float* __restrict__ k,
                    const float* __restrict__ v,
                    const float* __restrict__ wq, const float* __restrict__ wk,
                    const float* __restrict__ wv, const float* __restrict__ wo) {
    const int z = blockIdx.y;
    const size_t stride = (size_t)gridDim.x * blockDim.x;
    if (z < 3) {
        const float* src = (z == 0) ? q : (z == 1) ? k : v;
        __half* dst = (z == 0) ? g_aq : (z == 1) ? g_ak : g_av;
        const size_t n4 = NELEM / 4;
        for (size_t i = (size_t)blockIdx.x * blockDim.x + threadIdx.x; i < n4; i += stride)
            cvt4_store(((const float4*)src)[i], dst, i);
    } else {
        const float* wsrc[4] = {wq, wk, wv, wo};
        const size_t w4 = WELEM / 4;
        const size_t n4 = 4 * w4;
        for (size_t i = (size_t)blockIdx.x * blockDim.x + threadIdx.x; i < n4; i += stride) {
            const int w = (int)(i / w4);
            const size_t off = i % w4;
            cvt4_store(((const float4*)wsrc[w])[off], g_w[w], off);
        }
    }
}

// ---------------- per-token head attention, 2x2 tiling, fp16 inputs ----------------
// 4 tokens per 256-thread block; 64 threads per token (hp = s64>>3, gp/cp = s64&7).
// q/k/v read as fp16; k/v expanded to fp32 smem (same layouts as before), q
// converted in-register from L1. Compute all fp32. Output fp16 scrambled.
__global__ __launch_bounds__(256)
void attn_kernel() {
    extern __shared__ float asmem[];
    const int t    = threadIdx.x;
    const int grp  = t >> 6;       // token slot in block
    const int s64  = t & 63;
    const int token = blockIdx.x * ATOK + grp;
    const int b = token >> 12;
    const int s = token & 4095;

    float* ks = asmem + grp * TOK_F;
    float* vs = ks + 1024;
    float* at = vs + 1024;         // [16][17]

    const size_t base = (size_t)token * 1024;
    const uint2* gq2 = (const uint2*)(g_q + base);   // 4 halfs per slot
    {
        const uint2* gk2 = (const uint2*)(g_k + base);
        const uint2* gv2 = (const uint2*)(g_v + base);
#pragma unroll
        for (int i = 0; i < 4; i++) {
            const int slot = s64 + i * 64;           // 0..255
            const int r = slot >> 4, c = slot & 15;
            ((float4*)vs)[slot] = h4_to_f4(gv2[slot]);
            ((float4*)ks)[r * 16 + (c ^ ((r >> 1) & 7))] = h4_to_f4(gk2[slot]);
        }
    }
    __syncthreads();

    const int hp = s64 >> 3;       // 0..7
    const int gp = s64 & 7;        // 0..7

    // ---- score phase: 2x2 tile, d ascending; q from L1 (fp16), k via swizzled smem ----
    {
        float a00 = 0.f, a01 = 0.f, a10 = 0.f, a11 = 0.f;
        const float4* k4 = (const float4*)ks;
#pragma unroll
        for (int j = 0; j < 16; j++) {
            const int js = j ^ gp;
            float4 q0 = h4_to_f4(gq2[(2 * hp) * 16 + j]);
            float4 q1 = h4_to_f4(gq2[(2 * hp + 1) * 16 + j]);
            float4 k0 = k4[(2 * gp) * 16 + js];
            float4 k1 = k4[(2 * gp + 1) * 16 + js];
            a00 += q0.x * k0.x + q0.y * k0.y + q0.z * k0.z + q0.w * k0.w;
            a01 += q0.x * k1.x + q0.y * k1.y + q0.z * k1.z + q0.w * k1.w;
            a10 += q1.x * k0.x + q1.y * k0.y + q1.z * k0.z + q1.w * k0.w;
            a11 += q1.x * k1.x + q1.y * k1.y + q1.z * k1.z + q1.w * k1.w;
        }
        at[(2 * hp) * 17 + 2 * gp]         = a00 * 0.125f;
        at[(2 * hp) * 17 + 2 * gp + 1]     = a01 * 0.125f;
        at[(2 * hp + 1) * 17 + 2 * gp]     = a10 * 0.125f;
        at[(2 * hp + 1) * 17 + 2 * gp + 1] = a11 * 0.125f;
    }
    __syncthreads();

    // ---- softmax: 16 threads per token, one row each ----
    if (s64 < 16) {
        float* row = at + s64 * 17;
        float mx = row[0];
#pragma unroll
        for (int j = 1; j < 16; j++) mx = fmaxf(mx, row[j]);
        float p[16];
        float sum = 0.f;
#pragma unroll
        for (int j = 0; j < 16; j++) { p[j] = __expf(row[j] - mx); sum += p[j]; }
        const float inv = 1.f / sum;
#pragma unroll
        for (int j = 0; j < 16; j++) row[j] = p[j] * inv;
    }
    __syncthreads();

    // ---- AV phase: rows {2hp,2hp+1}, float4-cols {cp, cp+8}, gg ascending ----
    const int cp = gp;
    float4 o00 = make_float4(0.f, 0.f, 0.f, 0.f), o01 = o00, o10 = o00, o11 = o00;
    const float4* v4 = (const float4*)vs;
#pragma unroll
    for (int gg = 0; gg < 16; gg++) {
        const float w0 = at[(2 * hp) * 17 + gg];
        const float w1 = at[(2 * hp + 1) * 17 + gg];
        const float4 va = v4[gg * 16 + cp];
        const float4 vb = v4[gg * 16 + cp + 8];
        o00.x += w0 * va.x; o00.y += w0 * va.y; o00.z += w0 * va.z; o00.w += w0 * va.w;
        o01.x += w0 * vb.x; o01.y += w0 * vb.y; o01.z += w0 * vb.z; o01.w += w0 * vb.w;
        o10.x += w1 * va.x; o10.y += w1 * va.y; o10.z += w1 * va.z; o10.w += w1 * va.w;
        o11.x += w1 * vb.x; o11.y += w1 * vb.y; o11.z += w1 * vb.z; o11.w += w1 * vb.w;
    }

    // scrambled layout, fp16 (feeds the fp16 out-GEMM)
    const int scol = (s & 15) * 64;
    const int srow = s >> 4;
#pragma unroll
    for (int e = 0; e < 2; e++) {
        const int h2 = 2 * hp + e;
        const size_t row = (size_t)b * 4096 + (size_t)h2 * 256 + srow;
        float4 oa = e ? o10 : o00;
        float4 ob = e ? o11 : o01;
        __half2 a0 = __floats2half2_rn(oa.x, oa.y);
        __half2 a1 = __floats2half2_rn(oa.z, oa.w);
        __half2 b0 = __floats2half2_rn(ob.x, ob.y);
        __half2 b1 = __floats2half2_rn(ob.z, ob.w);
        const size_t idx = row * 1024 + scol;
        *(uint2*)(g_x + idx + cp * 4)       = make_uint2(*(uint32_t*)&a0, *(uint32_t*)&a1);
        *(uint2*)(g_x + idx + (cp + 8) * 4) = make_uint2(*(uint32_t*)&b0, *(uint32_t*)&b1);
    }
}

// ---------------- launch ----------------
extern "C" void kernel_launch(void* const* d_in, const int* in_sizes, int n_in,
                              void* d_out, int out_size) {
    (void)in_sizes; (void)n_in; (void)out_size;
    const float* query = (const float*)d_in[0];
    const float* key   = (const float*)d_in[1];
    const float* value = (const float*)d_in[2];
    const float* Wq = (const float*)d_in[3];
    const float* bq = (const float*)d_in[4];
    const float* Wk = (const float*)d_in[5];
    const float* bk = (const float*)d_in[6];
    const float* Wv = (const float*)d_in[7];
    const float* bv = (const float*)d_in[8];
    const float* Wo = (const float*)d_in[9];
    const float* bo = (const float*)d_in[10];
    float* out = (float*)d_out;

    cudaFuncSetAttribute(qkv_mma_kernel, cudaFuncAttributeMaxDynamicSharedMemorySize, SMEM_DYN);
    cudaFuncSetAttribute(out_mma_kernel, cudaFuncAttributeMaxDynamicSharedMemorySize, SMEM_DYN);
    cudaFuncSetAttribute(attn_kernel, cudaFuncAttributeMaxDynamicSharedMemorySize, ATTN_SMEM);

    cvt_all_kernel<<<dim3(4096, 4), 256>>>(query, key, value, Wq, Wk, Wv, Wo);
    qkv_mma_kernel<<<dim3(KD / TN, MDIM / TMC, 3), NTHR, SMEM_DYN>>>(bq, bk, bv);
    attn_kernel<<<MDIM / ATOK, 256, ATTN_SMEM>>>();
    out_mma_kernel<<<dim3(KD / TN, MDIM / TMC, 1), NTHR, SMEM_DYN>>>(bo, out);
}